// round 2
// baseline (speedup 1.0000x reference)
#include <cuda_runtime.h>
#include <cstdint>

#define LQ 43054
#define D  256
#define NH 8
#define NL 4
#define NP 4
#define HD 32

// ---------------- scratch (device globals; no allocation allowed) ----------------
__device__ float g_q   [LQ * D];   // query + pos
__device__ float g_val [LQ * D];   // value projection
__device__ float g_off [LQ * 256]; // sampling offsets
__device__ float g_lgt [LQ * 128]; // attention logits
__device__ float g_acc [LQ * D];   // deformable attention output (pre w_out)
__device__ float g_x   [LQ * D];   // after LN1
__device__ float g_h   [LQ * D];   // FFN hidden
__device__ float g_f   [LQ * D];   // generic matmul output

// ---------------- elementwise add (float4) ----------------
__global__ void add_kernel(const float* __restrict__ a, const float* __restrict__ b,
                           float* __restrict__ c, int n4) {
    int i = blockIdx.x * blockDim.x + threadIdx.x;
    if (i >= n4) return;
    float4 va = reinterpret_cast<const float4*>(a)[i];
    float4 vb = reinterpret_cast<const float4*>(b)[i];
    float4 vc;
    vc.x = va.x + vb.x; vc.y = va.y + vb.y; vc.z = va.z + vb.z; vc.w = va.w + vb.w;
    reinterpret_cast<float4*>(c)[i] = vc;
}

// ---------------- SIMT fp32 GEMM, BK=16, double-buffered smem ----------------
// C[M,N] = A[M,256] @ B[256,N] + bias, opt ReLU. BM=BN=128, 256 thr, 8x8/thread.
__global__ __launch_bounds__(256)
void sgemm128(const float* __restrict__ A, const float* __restrict__ B,
              const float* __restrict__ bias, float* __restrict__ C,
              int M, int N, int relu) {
    constexpr int K = 256;
    __shared__ __align__(16) float As[2][16][132];   // [k][m], padded
    __shared__ __align__(16) float Bs[2][16][128];   // [k][n]

    int tid = threadIdx.x;
    int bm = blockIdx.y * 128;
    int bn = blockIdx.x * 128;
    int tx = tid & 15;
    int ty = tid >> 4;

    float acc[8][8];
    #pragma unroll
    for (int i = 0; i < 8; i++)
        #pragma unroll
        for (int j = 0; j < 8; j++) acc[i][j] = 0.f;

    // A tile 128x16 = 512 float4 slots; thread owns slots tid and tid+256.
    int ar0 = tid >> 2;              // 0..63
    int ak  = (tid & 3) * 4;         // 0,4,8,12
    int ar1 = ar0 + 64;
    // B tile 16x128 = 512 float4 slots; thread owns slots tid and tid+256.
    int bk = tid >> 5;               // 0..7
    int bc = (tid & 31) * 4;

    float4 a0, a1, b0, b1;

    auto fetch = [&](int k0) {
        int r0 = bm + ar0;
        a0 = (r0 < M) ? *reinterpret_cast<const float4*>(A + (size_t)r0 * K + k0 + ak)
                      : make_float4(0.f, 0.f, 0.f, 0.f);
        int r1 = bm + ar1;
        a1 = (r1 < M) ? *reinterpret_cast<const float4*>(A + (size_t)r1 * K + k0 + ak)
                      : make_float4(0.f, 0.f, 0.f, 0.f);
        b0 = *reinterpret_cast<const float4*>(B + (size_t)(k0 + bk) * N + bn + bc);
        b1 = *reinterpret_cast<const float4*>(B + (size_t)(k0 + bk + 8) * N + bn + bc);
    };
    auto stage = [&](int buf) {
        As[buf][ak + 0][ar0] = a0.x;
        As[buf][ak + 1][ar0] = a0.y;
        As[buf][ak + 2][ar0] = a0.z;
        As[buf][ak + 3][ar0] = a0.w;
        As[buf][ak + 0][ar1] = a1.x;
        As[buf][ak + 1][ar1] = a1.y;
        As[buf][ak + 2][ar1] = a1.z;
        As[buf][ak + 3][ar1] = a1.w;
        *reinterpret_cast<float4*>(&Bs[buf][bk][bc]) = b0;
        *reinterpret_cast<float4*>(&Bs[buf][bk + 8][bc]) = b1;
    };

    fetch(0);
    stage(0);
    __syncthreads();

    #pragma unroll
    for (int t = 0; t < 16; t++) {
        if (t < 15) fetch((t + 1) * 16);
        int cur = t & 1;
        #pragma unroll
        for (int k = 0; k < 16; k++) {
            float ra[8], rb[8];
            float4 av0 = *reinterpret_cast<const float4*>(&As[cur][k][ty * 8]);
            float4 av1 = *reinterpret_cast<const float4*>(&As[cur][k][ty * 8 + 4]);
            ra[0]=av0.x; ra[1]=av0.y; ra[2]=av0.z; ra[3]=av0.w;
            ra[4]=av1.x; ra[5]=av1.y; ra[6]=av1.z; ra[7]=av1.w;
            float4 bv0 = *reinterpret_cast<const float4*>(&Bs[cur][k][tx * 8]);
            float4 bv1 = *reinterpret_cast<const float4*>(&Bs[cur][k][tx * 8 + 4]);
            rb[0]=bv0.x; rb[1]=bv0.y; rb[2]=bv0.z; rb[3]=bv0.w;
            rb[4]=bv1.x; rb[5]=bv1.y; rb[6]=bv1.z; rb[7]=bv1.w;
            #pragma unroll
            for (int i = 0; i < 8; i++)
                #pragma unroll
                for (int j = 0; j < 8; j++)
                    acc[i][j] += ra[i] * rb[j];
        }
        if (t < 15) stage((t + 1) & 1);
        __syncthreads();
    }

    #pragma unroll
    for (int i = 0; i < 8; i++) {
        int gr = bm + ty * 8 + i;
        if (gr >= M) continue;
        #pragma unroll
        for (int j0 = 0; j0 < 8; j0 += 4) {
            int gc = bn + tx * 8 + j0;
            float4 v;
            v.x = acc[i][j0 + 0] + bias[gc + 0];
            v.y = acc[i][j0 + 1] + bias[gc + 1];
            v.z = acc[i][j0 + 2] + bias[gc + 2];
            v.w = acc[i][j0 + 3] + bias[gc + 3];
            if (relu) {
                v.x = fmaxf(v.x, 0.f); v.y = fmaxf(v.y, 0.f);
                v.z = fmaxf(v.z, 0.f); v.w = fmaxf(v.w, 0.f);
            }
            *reinterpret_cast<float4*>(C + (size_t)gr * N + gc) = v;
        }
    }
}

// ---------------- deformable sampling + softmax (branch-free) ----------------
// block = one query, warp = one head, lane = channel (0..31)
__global__ __launch_bounds__(256)
void sample_kernel(const float* __restrict__ val,    // (LQ, 256)
                   const float* __restrict__ refp,   // (LQ, NL, 2)
                   const float* __restrict__ off,    // (LQ, 256)
                   const float* __restrict__ lgt,    // (LQ, 128)
                   const int* __restrict__ shapes,   // (NL, 2) [H, W]
                   const int* __restrict__ starts,   // (NL,)
                   float* __restrict__ acc) {
    int lq = blockIdx.x;
    int h  = threadIdx.x >> 5;
    int lane = threadIdx.x & 31;
    const unsigned FULL = 0xffffffffu;

    // cooperative softmax over 16 logits: lane i (i<16) owns logit i
    const float* lg = lgt + (size_t)lq * 128 + h * 16;
    float myl = (lane < 16) ? lg[lane] : -1e30f;
    float mx = myl;
    #pragma unroll
    for (int o = 8; o; o >>= 1) mx = fmaxf(mx, __shfl_xor_sync(FULL, mx, o));
    float e = (lane < 16) ? __expf(myl - mx) : 0.f;
    float sum = e;
    #pragma unroll
    for (int o = 8; o; o >>= 1) sum += __shfl_xor_sync(FULL, sum, o);
    float inv = 1.f / __shfl_sync(FULL, sum, 0);

    const float* op = off + (size_t)lq * 256 + h * 32;  // (l, p, 2)
    const float* rp = refp + (size_t)lq * 8;
    float a = 0.f;

    #pragma unroll
    for (int l = 0; l < NL; l++) {
        int Hl = __ldg(&shapes[l * 2 + 0]);
        int Wl = __ldg(&shapes[l * 2 + 1]);
        int st = __ldg(&starts[l]);
        float fW = (float)Wl, fH = (float)Hl;
        float bx = rp[l * 2 + 0] * fW - 0.5f;
        float by = rp[l * 2 + 1] * fH - 0.5f;
        #pragma unroll
        for (int p = 0; p < NP; p++) {
            float ox = op[(l * NP + p) * 2 + 0];
            float oy = op[(l * NP + p) * 2 + 1];
            float x = bx + ox;
            float y = by + oy;
            float x0f = floorf(x), y0f = floorf(y);
            float fx = x - x0f, fy = y - y0f;
            int x0 = (int)x0f, y0 = (int)y0f;
            float aw = __shfl_sync(FULL, e, l * NP + p) * inv;
            #pragma unroll
            for (int dy = 0; dy < 2; dy++) {
                #pragma unroll
                for (int dx = 0; dx < 2; dx++) {
                    int xi = x0 + dx, yi = y0 + dy;
                    bool valid = ((unsigned)xi < (unsigned)Wl) & ((unsigned)yi < (unsigned)Hl);
                    float wt = valid ? ((dx ? fx : 1.f - fx) * (dy ? fy : 1.f - fy)) * aw : 0.f;
                    int xc = min(max(xi, 0), Wl - 1);
                    int yc = min(max(yi, 0), Hl - 1);
                    const float* vp = val + ((size_t)(st + yc * Wl + xc) * 256 + h * 32);
                    a += wt * vp[lane];
                }
            }
        }
    }
    acc[(size_t)lq * 256 + h * 32 + lane] = a;
}

// ---------------- fused residual + LayerNorm (warp per row) ----------------
__global__ __launch_bounds__(256)
void ln_kernel(const float* __restrict__ res, const float* __restrict__ y,
               const float* __restrict__ g, const float* __restrict__ b,
               float* __restrict__ out, int M) {
    int warp = (blockIdx.x * blockDim.x + threadIdx.x) >> 5;
    int lane = threadIdx.x & 31;
    if (warp >= M) return;
    const float* r  = res + (size_t)warp * 256;
    const float* yy = y   + (size_t)warp * 256;
    float v[8];
    float s = 0.f;
    #pragma unroll
    for (int i = 0; i < 8; i++) {
        v[i] = r[lane + 32 * i] + yy[lane + 32 * i];
        s += v[i];
    }
    #pragma unroll
    for (int o = 16; o; o >>= 1) s += __shfl_xor_sync(0xffffffffu, s, o);
    float m = s * (1.f / 256.f);
    float vs = 0.f;
    #pragma unroll
    for (int i = 0; i < 8; i++) { float d = v[i] - m; vs += d * d; }
    #pragma unroll
    for (int o = 16; o; o >>= 1) vs += __shfl_xor_sync(0xffffffffu, vs, o);
    float rs = rsqrtf(vs * (1.f / 256.f) + 1e-5f);
    #pragma unroll
    for (int i = 0; i < 8; i++) {
        int c = lane + 32 * i;
        out[(size_t)warp * 256 + c] = (v[i] - m) * rs * g[c] + b[c];
    }
}

// ---------------- host ----------------
extern "C" void kernel_launch(void* const* d_in, const int* in_sizes, int n_in,
                              void* d_out, int out_size) {
    const float* query = (const float*)d_in[0];
    const float* refp  = (const float*)d_in[1];
    const float* pos   = (const float*)d_in[2];
    const int*   shp   = (const int*)d_in[3];
    const int*   sti   = (const int*)d_in[4];
    const float* w_off = (const float*)d_in[5];
    const float* b_off = (const float*)d_in[6];
    const float* w_attn= (const float*)d_in[7];
    const float* b_attn= (const float*)d_in[8];
    const float* w_val = (const float*)d_in[9];
    const float* b_val = (const float*)d_in[10];
    const float* w_out = (const float*)d_in[11];
    const float* b_out = (const float*)d_in[12];
    const float* g1    = (const float*)d_in[13];
    const float* be1   = (const float*)d_in[14];
    const float* w1    = (const float*)d_in[15];
    const float* b1    = (const float*)d_in[16];
    const float* w2    = (const float*)d_in[17];
    const float* b2    = (const float*)d_in[18];
    const float* g2    = (const float*)d_in[19];
    const float* be2   = (const float*)d_in[20];
    float* out = (float*)d_out;

    float *q, *val, *off, *lgt, *acc, *x, *h, *f;
    cudaGetSymbolAddress((void**)&q,   g_q);
    cudaGetSymbolAddress((void**)&val, g_val);
    cudaGetSymbolAddress((void**)&off, g_off);
    cudaGetSymbolAddress((void**)&lgt, g_lgt);
    cudaGetSymbolAddress((void**)&acc, g_acc);
    cudaGetSymbolAddress((void**)&x,   g_x);
    cudaGetSymbolAddress((void**)&h,   g_h);
    cudaGetSymbolAddress((void**)&f,   g_f);

    const int M = LQ;
    dim3 gemm_grid_256(2, (M + 127) / 128);
    dim3 gemm_grid_128(1, (M + 127) / 128);

    {
        int n4 = (LQ * D) / 4;
        add_kernel<<<(n4 + 255) / 256, 256>>>(query, pos, q, n4);
    }
    sgemm128<<<gemm_grid_256, 256>>>(query, w_val, b_val, val, M, 256, 0);
    sgemm128<<<gemm_grid_256, 256>>>(q, w_off, b_off, off, M, 256, 0);
    sgemm128<<<gemm_grid_128, 256>>>(q, w_attn, b_attn, lgt, M, 128, 0);
    sample_kernel<<<LQ, 256>>>(val, refp, off, lgt, shp, sti, acc);
    sgemm128<<<gemm_grid_256, 256>>>(acc, w_out, b_out, f, M, 256, 0);
    {
        int blocks = (M * 32 + 255) / 256;
        ln_kernel<<<blocks, 256>>>(query, f, g1, be1, x, M);
    }
    sgemm128<<<gemm_grid_256, 256>>>(x, w1, b1, h, M, 256, 1);
    sgemm128<<<gemm_grid_256, 256>>>(h, w2, b2, f, M, 256, 0);
    {
        int blocks = (M * 32 + 255) / 256;
        ln_kernel<<<blocks, 256>>>(x, f, g2, be2, out, M);
    }
}

// round 3
// speedup vs baseline: 1.7278x; 1.7278x over previous
#include <cuda_runtime.h>
#include <cstdint>

#define LQ 43054
#define D  256
#define NH 8
#define NL 4
#define NP 4
#define HD 32

// ---------------- scratch (device globals; no allocation allowed) ----------------
__device__ float g_q   [LQ * D];
__device__ float g_val [LQ * D];
__device__ float g_off [LQ * 256];
__device__ float g_lgt [LQ * 128];
__device__ float g_acc [LQ * D];
__device__ float g_x   [LQ * D];
__device__ float g_h   [LQ * D];
__device__ float g_f   [LQ * D];

// ---------------- elementwise add (float4) ----------------
__global__ void add_kernel(const float* __restrict__ a, const float* __restrict__ b,
                           float* __restrict__ c, int n4) {
    int i = blockIdx.x * blockDim.x + threadIdx.x;
    if (i >= n4) return;
    float4 va = reinterpret_cast<const float4*>(a)[i];
    float4 vb = reinterpret_cast<const float4*>(b)[i];
    float4 vc;
    vc.x = va.x + vb.x; vc.y = va.y + vb.y; vc.z = va.z + vb.z; vc.w = va.w + vb.w;
    reinterpret_cast<float4*>(c)[i] = vc;
}

// ---------------- SIMT fp32 GEMM (R1 version, BK=8) ----------------
__global__ __launch_bounds__(256)
void sgemm128(const float* __restrict__ A, const float* __restrict__ B,
              const float* __restrict__ bias, float* __restrict__ C,
              int M, int N, int relu) {
    constexpr int K = 256;
    __shared__ float As[8][128];
    __shared__ float Bs[8][128];

    int tid = threadIdx.x;
    int bm = blockIdx.y * 128;
    int bn = blockIdx.x * 128;
    int tx = tid & 15;
    int ty = tid >> 4;

    float acc[8][8];
    #pragma unroll
    for (int i = 0; i < 8; i++)
        #pragma unroll
        for (int j = 0; j < 8; j++) acc[i][j] = 0.f;

    int a_row = tid >> 1;
    int a_col = (tid & 1) * 4;
    int b_row = tid >> 5;
    int b_col = (tid & 31) * 4;

    for (int k0 = 0; k0 < K; k0 += 8) {
        float4 av = make_float4(0.f, 0.f, 0.f, 0.f);
        int gr = bm + a_row;
        if (gr < M)
            av = *reinterpret_cast<const float4*>(A + (size_t)gr * K + k0 + a_col);
        As[a_col + 0][a_row] = av.x;
        As[a_col + 1][a_row] = av.y;
        As[a_col + 2][a_row] = av.z;
        As[a_col + 3][a_row] = av.w;

        float4 bv = *reinterpret_cast<const float4*>(B + (size_t)(k0 + b_row) * N + bn + b_col);
        *reinterpret_cast<float4*>(&Bs[b_row][b_col]) = bv;
        __syncthreads();

        #pragma unroll
        for (int k = 0; k < 8; k++) {
            float ra[8], rb[8];
            float4 a0 = *reinterpret_cast<const float4*>(&As[k][ty * 8]);
            float4 a1 = *reinterpret_cast<const float4*>(&As[k][ty * 8 + 4]);
            ra[0]=a0.x; ra[1]=a0.y; ra[2]=a0.z; ra[3]=a0.w;
            ra[4]=a1.x; ra[5]=a1.y; ra[6]=a1.z; ra[7]=a1.w;
            float4 b0 = *reinterpret_cast<const float4*>(&Bs[k][tx * 8]);
            float4 b1 = *reinterpret_cast<const float4*>(&Bs[k][tx * 8 + 4]);
            rb[0]=b0.x; rb[1]=b0.y; rb[2]=b0.z; rb[3]=b0.w;
            rb[4]=b1.x; rb[5]=b1.y; rb[6]=b1.z; rb[7]=b1.w;
            #pragma unroll
            for (int i = 0; i < 8; i++)
                #pragma unroll
                for (int j = 0; j < 8; j++)
                    acc[i][j] += ra[i] * rb[j];
        }
        __syncthreads();
    }

    #pragma unroll
    for (int i = 0; i < 8; i++) {
        int gr = bm + ty * 8 + i;
        if (gr >= M) continue;
        #pragma unroll
        for (int j0 = 0; j0 < 8; j0 += 4) {
            int gc = bn + tx * 8 + j0;
            float4 v;
            v.x = acc[i][j0 + 0] + bias[gc + 0];
            v.y = acc[i][j0 + 1] + bias[gc + 1];
            v.z = acc[i][j0 + 2] + bias[gc + 2];
            v.w = acc[i][j0 + 3] + bias[gc + 3];
            if (relu) {
                v.x = fmaxf(v.x, 0.f); v.y = fmaxf(v.y, 0.f);
                v.z = fmaxf(v.z, 0.f); v.w = fmaxf(v.w, 0.f);
            }
            *reinterpret_cast<float4*>(C + (size_t)gr * N + gc) = v;
        }
    }
}

// ---------------- deformable sampling: precompute (addr, weight), then stream ----
// block = one query; 256 threads; warp h = head h in phase 2.
__global__ __launch_bounds__(256)
void sample_kernel(const float* __restrict__ val,    // (LQ, 256)
                   const float* __restrict__ refp,   // (LQ, NL, 2)
                   const float* __restrict__ off,    // (LQ, 256)
                   const float* __restrict__ lgt,    // (LQ, 128)
                   const int* __restrict__ shapes,   // (NL, 2) [H, W]
                   const int* __restrict__ starts,   // (NL,)
                   float* __restrict__ acc) {
    __shared__ float aw_s[NH * 16];        // softmax weights
    __shared__ int2  pw_s[512];            // (addr, weight-bits) per corner

    int lq = blockIdx.x;
    int tid = threadIdx.x;
    int h = tid >> 5;
    int lane = tid & 31;
    const unsigned FULL = 0xffffffffu;

    // ---- phase 0: softmax per head (warp h handles head h) ----
    {
        const float* lg = lgt + (size_t)lq * 128 + h * 16;
        float myl = (lane < 16) ? lg[lane] : -1e30f;
        float mx = myl;
        #pragma unroll
        for (int o = 8; o; o >>= 1) mx = fmaxf(mx, __shfl_xor_sync(FULL, mx, o));
        float e = (lane < 16) ? __expf(myl - mx) : 0.f;
        float sum = e;
        #pragma unroll
        for (int o = 16; o; o >>= 1) sum += __shfl_xor_sync(FULL, sum, o);
        float inv = 1.f / sum;
        if (lane < 16) aw_s[h * 16 + lane] = e * inv;
    }
    __syncthreads();

    // ---- phase 1: compute 512 (addr, weight) pairs; each thread does 2 ----
    #pragma unroll
    for (int rep = 0; rep < 2; rep++) {
        int j = tid + rep * 256;           // 0..511
        int jh = j >> 6;                   // head
        int rem = j & 63;
        int p = rem >> 2;                  // 0..15 = l*4 + pp
        int c = rem & 3;
        int dx = c & 1, dy = c >> 1;
        int l = p >> 2;

        int Hl = __ldg(&shapes[l * 2 + 0]);
        int Wl = __ldg(&shapes[l * 2 + 1]);
        int st = __ldg(&starts[l]);
        float fW = (float)Wl, fH = (float)Hl;

        float rx = __ldg(&refp[(size_t)lq * 8 + l * 2 + 0]);
        float ry = __ldg(&refp[(size_t)lq * 8 + l * 2 + 1]);
        float ox = __ldg(&off[(size_t)lq * 256 + jh * 32 + p * 2 + 0]);
        float oy = __ldg(&off[(size_t)lq * 256 + jh * 32 + p * 2 + 1]);

        float x = rx * fW + ox - 0.5f;
        float y = ry * fH + oy - 0.5f;
        float x0f = floorf(x), y0f = floorf(y);
        float fx = x - x0f, fy = y - y0f;
        int xi = (int)x0f + dx;
        int yi = (int)y0f + dy;
        bool valid = ((unsigned)xi < (unsigned)Wl) & ((unsigned)yi < (unsigned)Hl);
        float wt = valid ? ((dx ? fx : 1.f - fx) * (dy ? fy : 1.f - fy)) * aw_s[jh * 16 + p]
                         : 0.f;
        int xc = min(max(xi, 0), Wl - 1);
        int yc = min(max(yi, 0), Hl - 1);
        int addr = (st + yc * Wl + xc) * 256 + jh * 32;
        pw_s[j] = make_int2(addr, __float_as_int(wt));
    }
    __syncthreads();

    // ---- phase 2: warp h streams its 64 (addr, weight) pairs ----
    {
        const int2* pw = pw_s + h * 64;
        float a0 = 0.f, a1 = 0.f, a2 = 0.f, a3 = 0.f;
        #pragma unroll
        for (int j0 = 0; j0 < 64; j0 += 8) {
            int2 q0 = pw[j0 + 0], q1 = pw[j0 + 1], q2 = pw[j0 + 2], q3 = pw[j0 + 3];
            int2 q4 = pw[j0 + 4], q5 = pw[j0 + 5], q6 = pw[j0 + 6], q7 = pw[j0 + 7];
            float v0 = __ldg(val + q0.x + lane);
            float v1 = __ldg(val + q1.x + lane);
            float v2 = __ldg(val + q2.x + lane);
            float v3 = __ldg(val + q3.x + lane);
            float v4 = __ldg(val + q4.x + lane);
            float v5 = __ldg(val + q5.x + lane);
            float v6 = __ldg(val + q6.x + lane);
            float v7 = __ldg(val + q7.x + lane);
            a0 += __int_as_float(q0.y) * v0;
            a1 += __int_as_float(q1.y) * v1;
            a2 += __int_as_float(q2.y) * v2;
            a3 += __int_as_float(q3.y) * v3;
            a0 += __int_as_float(q4.y) * v4;
            a1 += __int_as_float(q5.y) * v5;
            a2 += __int_as_float(q6.y) * v6;
            a3 += __int_as_float(q7.y) * v7;
        }
        acc[(size_t)lq * 256 + h * 32 + lane] = (a0 + a1) + (a2 + a3);
    }
}

// ---------------- fused residual + LayerNorm (warp per row) ----------------
__global__ __launch_bounds__(256)
void ln_kernel(const float* __restrict__ res, const float* __restrict__ y,
               const float* __restrict__ g, const float* __restrict__ b,
               float* __restrict__ out, int M) {
    int warp = (blockIdx.x * blockDim.x + threadIdx.x) >> 5;
    int lane = threadIdx.x & 31;
    if (warp >= M) return;
    const float* r  = res + (size_t)warp * 256;
    const float* yy = y   + (size_t)warp * 256;
    float v[8];
    float s = 0.f;
    #pragma unroll
    for (int i = 0; i < 8; i++) {
        v[i] = r[lane + 32 * i] + yy[lane + 32 * i];
        s += v[i];
    }
    #pragma unroll
    for (int o = 16; o; o >>= 1) s += __shfl_xor_sync(0xffffffffu, s, o);
    float m = s * (1.f / 256.f);
    float vs = 0.f;
    #pragma unroll
    for (int i = 0; i < 8; i++) { float d = v[i] - m; vs += d * d; }
    #pragma unroll
    for (int o = 16; o; o >>= 1) vs += __shfl_xor_sync(0xffffffffu, vs, o);
    float rs = rsqrtf(vs * (1.f / 256.f) + 1e-5f);
    #pragma unroll
    for (int i = 0; i < 8; i++) {
        int c = lane + 32 * i;
        out[(size_t)warp * 256 + c] = (v[i] - m) * rs * g[c] + b[c];
    }
}

// ---------------- host ----------------
extern "C" void kernel_launch(void* const* d_in, const int* in_sizes, int n_in,
                              void* d_out, int out_size) {
    const float* query = (const float*)d_in[0];
    const float* refp  = (const float*)d_in[1];
    const float* pos   = (const float*)d_in[2];
    const int*   shp   = (const int*)d_in[3];
    const int*   sti   = (const int*)d_in[4];
    const float* w_off = (const float*)d_in[5];
    const float* b_off = (const float*)d_in[6];
    const float* w_attn= (const float*)d_in[7];
    const float* b_attn= (const float*)d_in[8];
    const float* w_val = (const float*)d_in[9];
    const float* b_val = (const float*)d_in[10];
    const float* w_out = (const float*)d_in[11];
    const float* b_out = (const float*)d_in[12];
    const float* g1    = (const float*)d_in[13];
    const float* be1   = (const float*)d_in[14];
    const float* w1    = (const float*)d_in[15];
    const float* b1    = (const float*)d_in[16];
    const float* w2    = (const float*)d_in[17];
    const float* b2    = (const float*)d_in[18];
    const float* g2    = (const float*)d_in[19];
    const float* be2   = (const float*)d_in[20];
    float* out = (float*)d_out;

    float *q, *val, *off, *lgt, *acc, *x, *h, *f;
    cudaGetSymbolAddress((void**)&q,   g_q);
    cudaGetSymbolAddress((void**)&val, g_val);
    cudaGetSymbolAddress((void**)&off, g_off);
    cudaGetSymbolAddress((void**)&lgt, g_lgt);
    cudaGetSymbolAddress((void**)&acc, g_acc);
    cudaGetSymbolAddress((void**)&x,   g_x);
    cudaGetSymbolAddress((void**)&h,   g_h);
    cudaGetSymbolAddress((void**)&f,   g_f);

    const int M = LQ;
    dim3 gemm_grid_256(2, (M + 127) / 128);
    dim3 gemm_grid_128(1, (M + 127) / 128);

    {
        int n4 = (LQ * D) / 4;
        add_kernel<<<(n4 + 255) / 256, 256>>>(query, pos, q, n4);
    }
    sgemm128<<<gemm_grid_256, 256>>>(query, w_val, b_val, val, M, 256, 0);
    sgemm128<<<gemm_grid_256, 256>>>(q, w_off, b_off, off, M, 256, 0);
    sgemm128<<<gemm_grid_128, 256>>>(q, w_attn, b_attn, lgt, M, 128, 0);
    sample_kernel<<<LQ, 256>>>(val, refp, off, lgt, shp, sti, acc);
    sgemm128<<<gemm_grid_256, 256>>>(acc, w_out, b_out, f, M, 256, 0);
    {
        int blocks = (M * 32 + 255) / 256;
        ln_kernel<<<blocks, 256>>>(query, f, g1, be1, x, M);
    }
    sgemm128<<<gemm_grid_256, 256>>>(x, w1, b1, h, M, 256, 1);
    sgemm128<<<gemm_grid_256, 256>>>(h, w2, b2, f, M, 256, 0);
    {
        int blocks = (M * 32 + 255) / 256;
        ln_kernel<<<blocks, 256>>>(x, f, g2, be2, out, M);
    }
}

// round 4
// speedup vs baseline: 2.8738x; 1.6633x over previous
#include <cuda_runtime.h>
#include <cuda_bf16.h>
#include <cstdint>

#define LQ 43054
#define D  256
#define NH 8
#define NL 4
#define NP 4
#define HD 32

// ---------------- scratch (device globals) ----------------
__device__ float g_q   [LQ * D];
__device__ float g_val [LQ * D];
__device__ __nv_bfloat16 g_valh[LQ * D];
__device__ float g_off [LQ * 256];
__device__ float g_lgt [LQ * 128];
__device__ float g_acc [LQ * D];
__device__ float g_x   [LQ * D];
__device__ float g_h   [LQ * D];
__device__ float g_f   [LQ * D];

// ---------------- elementwise add (float4) ----------------
__global__ void add_kernel(const float* __restrict__ a, const float* __restrict__ b,
                           float* __restrict__ c, int n4) {
    int i = blockIdx.x * blockDim.x + threadIdx.x;
    if (i >= n4) return;
    float4 va = reinterpret_cast<const float4*>(a)[i];
    float4 vb = reinterpret_cast<const float4*>(b)[i];
    float4 vc;
    vc.x = va.x + vb.x; vc.y = va.y + vb.y; vc.z = va.z + vb.z; vc.w = va.w + vb.w;
    reinterpret_cast<float4*>(c)[i] = vc;
}

// ---------------- fp32 -> bf16 convert (8 elems/thread) ----------------
__global__ void cvt_bf16_kernel(const float* __restrict__ in,
                                __nv_bfloat16* __restrict__ outp, int n8) {
    int i = blockIdx.x * blockDim.x + threadIdx.x;
    if (i >= n8) return;
    float4 v0 = reinterpret_cast<const float4*>(in)[i * 2 + 0];
    float4 v1 = reinterpret_cast<const float4*>(in)[i * 2 + 1];
    __nv_bfloat162 b0 = __floats2bfloat162_rn(v0.x, v0.y);
    __nv_bfloat162 b1 = __floats2bfloat162_rn(v0.z, v0.w);
    __nv_bfloat162 b2 = __floats2bfloat162_rn(v1.x, v1.y);
    __nv_bfloat162 b3 = __floats2bfloat162_rn(v1.z, v1.w);
    uint4 pack;
    pack.x = *reinterpret_cast<uint32_t*>(&b0);
    pack.y = *reinterpret_cast<uint32_t*>(&b1);
    pack.z = *reinterpret_cast<uint32_t*>(&b2);
    pack.w = *reinterpret_cast<uint32_t*>(&b3);
    reinterpret_cast<uint4*>(outp)[i] = pack;
}

// ---------------- TF32 tensor-core GEMM ----------------
// C[M,N] = A[M,256] @ B[256,N] + bias, opt ReLU. BM=128, BN=128, BK=32.
// 256 threads = 8 warps (2x4); warp tile 64x32; mma.m16n8k8.tf32.
__device__ __forceinline__ uint32_t cvt_tf32(float f) {
    uint32_t r;
    asm("cvt.rna.tf32.f32 %0, %1;" : "=r"(r) : "f"(f));
    return r;
}

__global__ __launch_bounds__(256, 2)
void tgemm(const float* __restrict__ A, const float* __restrict__ B,
           const float* __restrict__ bias, float* __restrict__ C,
           int M, int N, int relu) {
    constexpr int K = 256;
    constexpr int LDS = 36;                 // padded row stride (floats)
    __shared__ __align__(16) float As[128 * LDS];
    __shared__ __align__(16) float Bs[128 * LDS];

    int tid = threadIdx.x;
    int lane = tid & 31;
    int wid = tid >> 5;
    int bm = blockIdx.y * 128;
    int bn = blockIdx.x * 128;
    int wm = (wid >> 2) * 64;               // 0 / 64
    int wn = (wid & 3) * 32;                // 0 / 32 / 64 / 96

    float c[4][4][4];
    #pragma unroll
    for (int i = 0; i < 4; i++)
        #pragma unroll
        for (int j = 0; j < 4; j++)
            #pragma unroll
            for (int r = 0; r < 4; r++) c[i][j][r] = 0.f;

    // ldmatrix source addresses (A and B use the same pattern)
    int fr_row = (lane & 7) + ((lane & 8) ? 8 : 0);
    int fr_kad = (lane & 16) ? 4 : 0;

    for (int k0 = 0; k0 < K; k0 += 32) {
        // stage A: 128 rows x 32 cols; 1024 float4 slots, 4 per thread
        #pragma unroll
        for (int i = 0; i < 4; i++) {
            int slot = tid + i * 256;
            int row = slot >> 3;
            int k4 = (slot & 7) * 4;
            float4 v = make_float4(0.f, 0.f, 0.f, 0.f);
            if (bm + row < M)
                v = *reinterpret_cast<const float4*>(A + (size_t)(bm + row) * K + k0 + k4);
            uint4 t;
            t.x = cvt_tf32(v.x); t.y = cvt_tf32(v.y);
            t.z = cvt_tf32(v.z); t.w = cvt_tf32(v.w);
            *reinterpret_cast<uint4*>(&As[row * LDS + k4]) = t;
        }
        // stage B transposed: Bs[n][k]; read float4 along n
        #pragma unroll
        for (int i = 0; i < 4; i++) {
            int slot = tid + i * 256;
            int kk = slot >> 5;             // 0..31
            int n4 = (slot & 31) * 4;
            float4 v = *reinterpret_cast<const float4*>(B + (size_t)(k0 + kk) * N + bn + n4);
            Bs[(n4 + 0) * LDS + kk] = __uint_as_float(cvt_tf32(v.x));
            Bs[(n4 + 1) * LDS + kk] = __uint_as_float(cvt_tf32(v.y));
            Bs[(n4 + 2) * LDS + kk] = __uint_as_float(cvt_tf32(v.z));
            Bs[(n4 + 3) * LDS + kk] = __uint_as_float(cvt_tf32(v.w));
        }
        __syncthreads();

        #pragma unroll
        for (int k8 = 0; k8 < 4; k8++) {
            int kbase = k8 * 8;
            uint32_t af[4][4];
            #pragma unroll
            for (int mf = 0; mf < 4; mf++) {
                const float* p = &As[(wm + mf * 16 + fr_row) * LDS + kbase + fr_kad];
                uint32_t addr = (uint32_t)__cvta_generic_to_shared(p);
                asm volatile("ldmatrix.sync.aligned.m8n8.x4.shared.b16 {%0,%1,%2,%3}, [%4];"
                             : "=r"(af[mf][0]), "=r"(af[mf][1]), "=r"(af[mf][2]), "=r"(af[mf][3])
                             : "r"(addr));
            }
            uint32_t bf[4][2];
            #pragma unroll
            for (int nf = 0; nf < 4; nf++) {
                const float* p = &Bs[(wn + nf * 8 + (lane & 7)) * LDS + kbase + ((lane & 8) ? 4 : 0)];
                uint32_t addr = (uint32_t)__cvta_generic_to_shared(p);
                asm volatile("ldmatrix.sync.aligned.m8n8.x2.shared.b16 {%0,%1}, [%2];"
                             : "=r"(bf[nf][0]), "=r"(bf[nf][1])
                             : "r"(addr));
            }
            #pragma unroll
            for (int mf = 0; mf < 4; mf++)
                #pragma unroll
                for (int nf = 0; nf < 4; nf++) {
                    asm volatile(
                        "mma.sync.aligned.m16n8k8.row.col.f32.tf32.tf32.f32 "
                        "{%0,%1,%2,%3}, {%4,%5,%6,%7}, {%8,%9}, {%0,%1,%2,%3};"
                        : "+f"(c[mf][nf][0]), "+f"(c[mf][nf][1]),
                          "+f"(c[mf][nf][2]), "+f"(c[mf][nf][3])
                        : "r"(af[mf][0]), "r"(af[mf][1]), "r"(af[mf][2]), "r"(af[mf][3]),
                          "r"(bf[nf][0]), "r"(bf[nf][1]));
                }
        }
        __syncthreads();
    }

    // epilogue
    #pragma unroll
    for (int mf = 0; mf < 4; mf++) {
        int row0 = bm + wm + mf * 16 + (lane >> 2);
        #pragma unroll
        for (int nf = 0; nf < 4; nf++) {
            int col = bn + wn + nf * 8 + (lane & 3) * 2;
            float bx = bias[col], by = bias[col + 1];
            float2 v0, v1;
            v0.x = c[mf][nf][0] + bx; v0.y = c[mf][nf][1] + by;
            v1.x = c[mf][nf][2] + bx; v1.y = c[mf][nf][3] + by;
            if (relu) {
                v0.x = fmaxf(v0.x, 0.f); v0.y = fmaxf(v0.y, 0.f);
                v1.x = fmaxf(v1.x, 0.f); v1.y = fmaxf(v1.y, 0.f);
            }
            if (row0 < M)
                *reinterpret_cast<float2*>(C + (size_t)row0 * N + col) = v0;
            if (row0 + 8 < M)
                *reinterpret_cast<float2*>(C + (size_t)(row0 + 8) * N + col) = v1;
        }
    }
}

// ---------------- deformable sampling (bf16 value, half-warp per corner) ----
__global__ __launch_bounds__(256)
void sample_kernel(const __nv_bfloat16* __restrict__ valh,  // (LQ, 256) bf16
                   const float* __restrict__ refp,          // (LQ, NL, 2)
                   const float* __restrict__ off,           // (LQ, 256)
                   const float* __restrict__ lgt,           // (LQ, 128)
                   const int* __restrict__ shapes,          // (NL, 2) [H, W]
                   const int* __restrict__ starts,          // (NL,)
                   float* __restrict__ acc) {
    __shared__ float aw_s[NH * 16];
    __shared__ int2  pw_s[512];

    int lq = blockIdx.x;
    int tid = threadIdx.x;
    int h = tid >> 5;
    int lane = tid & 31;
    const unsigned FULL = 0xffffffffu;

    // phase 0: softmax per head
    {
        const float* lg = lgt + (size_t)lq * 128 + h * 16;
        float myl = (lane < 16) ? lg[lane] : -1e30f;
        float mx = myl;
        #pragma unroll
        for (int o = 8; o; o >>= 1) mx = fmaxf(mx, __shfl_xor_sync(FULL, mx, o));
        float e = (lane < 16) ? __expf(myl - mx) : 0.f;
        float sum = e;
        #pragma unroll
        for (int o = 16; o; o >>= 1) sum += __shfl_xor_sync(FULL, sum, o);
        float inv = 1.f / sum;
        if (lane < 16) aw_s[h * 16 + lane] = e * inv;
    }
    __syncthreads();

    // phase 1: 512 (addr, weight) pairs; 2 per thread
    #pragma unroll
    for (int rep = 0; rep < 2; rep++) {
        int j = tid + rep * 256;
        int jh = j >> 6;
        int rem = j & 63;
        int p = rem >> 2;
        int cc = rem & 3;
        int dx = cc & 1, dy = cc >> 1;
        int l = p >> 2;

        int Hl = __ldg(&shapes[l * 2 + 0]);
        int Wl = __ldg(&shapes[l * 2 + 1]);
        int st = __ldg(&starts[l]);
        float fW = (float)Wl, fH = (float)Hl;

        float rx = __ldg(&refp[(size_t)lq * 8 + l * 2 + 0]);
        float ry = __ldg(&refp[(size_t)lq * 8 + l * 2 + 1]);
        float ox = __ldg(&off[(size_t)lq * 256 + jh * 32 + p * 2 + 0]);
        float oy = __ldg(&off[(size_t)lq * 256 + jh * 32 + p * 2 + 1]);

        float x = rx * fW + ox - 0.5f;
        float y = ry * fH + oy - 0.5f;
        float x0f = floorf(x), y0f = floorf(y);
        float fx = x - x0f, fy = y - y0f;
        int xi = (int)x0f + dx;
        int yi = (int)y0f + dy;
        bool valid = ((unsigned)xi < (unsigned)Wl) & ((unsigned)yi < (unsigned)Hl);
        float wt = valid ? ((dx ? fx : 1.f - fx) * (dy ? fy : 1.f - fy)) * aw_s[jh * 16 + p]
                         : 0.f;
        int xc = min(max(xi, 0), Wl - 1);
        int yc = min(max(yi, 0), Hl - 1);
        int addr = (st + yc * Wl + xc) * 256 + jh * 32;   // bf16 element index
        pw_s[j] = make_int2(addr, __float_as_int(wt));
    }
    __syncthreads();

    // phase 2: warp h streams 64 corners; half-warp per corner, lane -> 2 channels
    {
        const int2* pw = pw_s + h * 64;
        int hw = lane >> 4;        // half index: even/odd corners
        int sl = lane & 15;        // bf162 slot -> channels 2sl, 2sl+1
        const __nv_bfloat162* vh = reinterpret_cast<const __nv_bfloat162*>(valh);
        float sx0 = 0.f, sy0 = 0.f, sx1 = 0.f, sy1 = 0.f;
        #pragma unroll
        for (int j0 = 0; j0 < 64; j0 += 8) {
            int2 q0 = pw[j0 + 0 + hw];
            int2 q1 = pw[j0 + 2 + hw];
            int2 q2 = pw[j0 + 4 + hw];
            int2 q3 = pw[j0 + 6 + hw];
            __nv_bfloat162 v0 = __ldg(vh + (q0.x >> 1) + sl);
            __nv_bfloat162 v1 = __ldg(vh + (q1.x >> 1) + sl);
            __nv_bfloat162 v2 = __ldg(vh + (q2.x >> 1) + sl);
            __nv_bfloat162 v3 = __ldg(vh + (q3.x >> 1) + sl);
            float w0 = __int_as_float(q0.y);
            float w1 = __int_as_float(q1.y);
            float w2 = __int_as_float(q2.y);
            float w3 = __int_as_float(q3.y);
            float2 f0 = __bfloat1622float2(v0);
            float2 f1 = __bfloat1622float2(v1);
            float2 f2 = __bfloat1622float2(v2);
            float2 f3 = __bfloat1622float2(v3);
            sx0 += w0 * f0.x; sy0 += w0 * f0.y;
            sx1 += w1 * f1.x; sy1 += w1 * f1.y;
            sx0 += w2 * f2.x; sy0 += w2 * f2.y;
            sx1 += w3 * f3.x; sy1 += w3 * f3.y;
        }
        float tx = sx0 + sx1;
        float ty = sy0 + sy1;
        tx += __shfl_xor_sync(FULL, tx, 16);
        ty += __shfl_xor_sync(FULL, ty, 16);
        if (lane < 16) {
            float2 o; o.x = tx; o.y = ty;
            *reinterpret_cast<float2*>(acc + (size_t)lq * 256 + h * 32 + 2 * sl) = o;
        }
    }
}

// ---------------- fused residual + LayerNorm (warp per row) ----------------
__global__ __launch_bounds__(256)
void ln_kernel(const float* __restrict__ res, const float* __restrict__ y,
               const float* __restrict__ g, const float* __restrict__ b,
               float* __restrict__ out, int M) {
    int warp = (blockIdx.x * blockDim.x + threadIdx.x) >> 5;
    int lane = threadIdx.x & 31;
    if (warp >= M) return;
    const float* r  = res + (size_t)warp * 256;
    const float* yy = y   + (size_t)warp * 256;
    float v[8];
    float s = 0.f;
    #pragma unroll
    for (int i = 0; i < 8; i++) {
        v[i] = r[lane + 32 * i] + yy[lane + 32 * i];
        s += v[i];
    }
    #pragma unroll
    for (int o = 16; o; o >>= 1) s += __shfl_xor_sync(0xffffffffu, s, o);
    float m = s * (1.f / 256.f);
    float vs = 0.f;
    #pragma unroll
    for (int i = 0; i < 8; i++) { float d = v[i] - m; vs += d * d; }
    #pragma unroll
    for (int o = 16; o; o >>= 1) vs += __shfl_xor_sync(0xffffffffu, vs, o);
    float rs = rsqrtf(vs * (1.f / 256.f) + 1e-5f);
    #pragma unroll
    for (int i = 0; i < 8; i++) {
        int c = lane + 32 * i;
        out[(size_t)warp * 256 + c] = (v[i] - m) * rs * g[c] + b[c];
    }
}

// ---------------- host ----------------
extern "C" void kernel_launch(void* const* d_in, const int* in_sizes, int n_in,
                              void* d_out, int out_size) {
    const float* query = (const float*)d_in[0];
    const float* refp  = (const float*)d_in[1];
    const float* pos   = (const float*)d_in[2];
    const int*   shp   = (const int*)d_in[3];
    const int*   sti   = (const int*)d_in[4];
    const float* w_off = (const float*)d_in[5];
    const float* b_off = (const float*)d_in[6];
    const float* w_attn= (const float*)d_in[7];
    const float* b_attn= (const float*)d_in[8];
    const float* w_val = (const float*)d_in[9];
    const float* b_val = (const float*)d_in[10];
    const float* w_out = (const float*)d_in[11];
    const float* b_out = (const float*)d_in[12];
    const float* g1    = (const float*)d_in[13];
    const float* be1   = (const float*)d_in[14];
    const float* w1    = (const float*)d_in[15];
    const float* b1    = (const float*)d_in[16];
    const float* w2    = (const float*)d_in[17];
    const float* b2    = (const float*)d_in[18];
    const float* g2    = (const float*)d_in[19];
    const float* be2   = (const float*)d_in[20];
    float* out = (float*)d_out;

    float *q, *val, *off, *lgt, *acc, *x, *h, *f;
    __nv_bfloat16* valh;
    cudaGetSymbolAddress((void**)&q,   g_q);
    cudaGetSymbolAddress((void**)&val, g_val);
    cudaGetSymbolAddress((void**)&valh,g_valh);
    cudaGetSymbolAddress((void**)&off, g_off);
    cudaGetSymbolAddress((void**)&lgt, g_lgt);
    cudaGetSymbolAddress((void**)&acc, g_acc);
    cudaGetSymbolAddress((void**)&x,   g_x);
    cudaGetSymbolAddress((void**)&h,   g_h);
    cudaGetSymbolAddress((void**)&f,   g_f);

    const int M = LQ;
    dim3 grid_n256(2, (M + 127) / 128);
    dim3 grid_n128(1, (M + 127) / 128);

    {
        int n4 = (LQ * D) / 4;
        add_kernel<<<(n4 + 255) / 256, 256>>>(query, pos, q, n4);
    }
    tgemm<<<grid_n256, 256>>>(query, w_val, b_val, val, M, 256, 0);
    {
        int n8 = (LQ * D) / 8;
        cvt_bf16_kernel<<<(n8 + 255) / 256, 256>>>(val, valh, n8);
    }
    tgemm<<<grid_n256, 256>>>(q, w_off, b_off, off, M, 256, 0);
    tgemm<<<grid_n128, 256>>>(q, w_attn, b_attn, lgt, M, 128, 0);
    sample_kernel<<<LQ, 256>>>(valh, refp, off, lgt, shp, sti, acc);
    tgemm<<<grid_n256, 256>>>(acc, w_out, b_out, f, M, 256, 0);
    {
        int blocks = (M * 32 + 255) / 256;
        ln_kernel<<<blocks, 256>>>(query, f, g1, be1, x, M);
    }
    tgemm<<<grid_n256, 256>>>(x, w1, b1, h, M, 256, 1);
    tgemm<<<grid_n256, 256>>>(h, w2, b2, f, M, 256, 0);
    {
        int blocks = (M * 32 + 255) / 256;
        ln_kernel<<<blocks, 256>>>(x, f, g2, be2, out, M);
    }
}

// round 5
// speedup vs baseline: 3.6745x; 1.2786x over previous
#include <cuda_runtime.h>
#include <cuda_bf16.h>
#include <cstdint>

#define LQ 43054
#define D  256
#define NH 8
#define NL 4
#define NP 4
#define HD 32

// ---------------- scratch (device globals) ----------------
__device__ float g_q   [LQ * D];
__device__ __nv_bfloat16 g_valh[LQ * D];
__device__ float g_off [LQ * 256];
__device__ float g_lgt [LQ * 128];
__device__ float g_acc [LQ * D];
__device__ float g_x   [LQ * D];
__device__ float g_h   [LQ * D];
__device__ float g_f   [LQ * D];

// ---------------- elementwise add (float4) ----------------
__global__ void add_kernel(const float* __restrict__ a, const float* __restrict__ b,
                           float* __restrict__ c, int n4) {
    int i = blockIdx.x * blockDim.x + threadIdx.x;
    if (i >= n4) return;
    float4 va = reinterpret_cast<const float4*>(a)[i];
    float4 vb = reinterpret_cast<const float4*>(b)[i];
    float4 vc;
    vc.x = va.x + vb.x; vc.y = va.y + vb.y; vc.z = va.z + vb.z; vc.w = va.w + vb.w;
    reinterpret_cast<float4*>(c)[i] = vc;
}

// ---------------- TF32 tensor-core GEMM ----------------
// C[M,N] = A[M,256] @ B[256,N] + bias. BM=128, BN=128, BK=32.
// 256 threads = 8 warps (2x4); warp tile 64x32; mma.m16n8k8.tf32.
// mode: 0 = fp32 out, 1 = fp32+ReLU, 2 = bf16 out (to __nv_bfloat16*)
__device__ __forceinline__ uint32_t cvt_tf32(float f) {
    uint32_t r;
    asm("cvt.rna.tf32.f32 %0, %1;" : "=r"(r) : "f"(f));
    return r;
}

__global__ __launch_bounds__(256, 2)
void tgemm(const float* __restrict__ A, const float* __restrict__ B,
           const float* __restrict__ bias, void* __restrict__ Cv,
           int M, int N, int mode) {
    constexpr int K = 256;
    constexpr int LDA = 36;   // A row stride (floats), padded
    constexpr int LDB = 132;  // B row stride (floats), padded
    __shared__ __align__(16) float As[128 * LDA];
    __shared__ __align__(16) float Bs[32 * LDB];

    int tid = threadIdx.x;
    int lane = tid & 31;
    int wid = tid >> 5;
    int bm = blockIdx.y * 128;
    int bn = blockIdx.x * 128;
    int wm = (wid >> 2) * 64;
    int wn = (wid & 3) * 32;

    float c[4][4][4];
    #pragma unroll
    for (int i = 0; i < 4; i++)
        #pragma unroll
        for (int j = 0; j < 4; j++)
            #pragma unroll
            for (int r = 0; r < 4; r++) c[i][j][r] = 0.f;

    int fr_row = (lane & 7) + ((lane & 8) ? 8 : 0);
    int fr_kad = (lane & 16) ? 4 : 0;
    int bq = lane & 3;     // B fragment k within quad
    int bcol = lane >> 2;  // B fragment n

    for (int k0 = 0; k0 < K; k0 += 32) {
        // stage A: 128 rows x 32 cols
        #pragma unroll
        for (int i = 0; i < 4; i++) {
            int slot = tid + i * 256;
            int row = slot >> 3;
            int k4 = (slot & 7) * 4;
            float4 v = make_float4(0.f, 0.f, 0.f, 0.f);
            if (bm + row < M)
                v = *reinterpret_cast<const float4*>(A + (size_t)(bm + row) * K + k0 + k4);
            uint4 t;
            t.x = cvt_tf32(v.x); t.y = cvt_tf32(v.y);
            t.z = cvt_tf32(v.z); t.w = cvt_tf32(v.w);
            *reinterpret_cast<uint4*>(&As[row * LDA + k4]) = t;
        }
        // stage B un-transposed: Bs[k][n], float4 along n (conflict-free)
        #pragma unroll
        for (int i = 0; i < 4; i++) {
            int slot = tid + i * 256;
            int kk = slot >> 5;
            int n4 = (slot & 31) * 4;
            float4 v = *reinterpret_cast<const float4*>(B + (size_t)(k0 + kk) * N + bn + n4);
            uint4 t;
            t.x = cvt_tf32(v.x); t.y = cvt_tf32(v.y);
            t.z = cvt_tf32(v.z); t.w = cvt_tf32(v.w);
            *reinterpret_cast<uint4*>(&Bs[kk * LDB + n4]) = t;
        }
        __syncthreads();

        #pragma unroll
        for (int k8 = 0; k8 < 4; k8++) {
            int kbase = k8 * 8;
            uint32_t af[4][4];
            #pragma unroll
            for (int mf = 0; mf < 4; mf++) {
                const float* p = &As[(wm + mf * 16 + fr_row) * LDA + kbase + fr_kad];
                uint32_t addr = (uint32_t)__cvta_generic_to_shared(p);
                asm volatile("ldmatrix.sync.aligned.m8n8.x4.shared.b16 {%0,%1,%2,%3}, [%4];"
                             : "=r"(af[mf][0]), "=r"(af[mf][1]), "=r"(af[mf][2]), "=r"(af[mf][3])
                             : "r"(addr));
            }
            uint32_t bf[4][2];
            #pragma unroll
            for (int nf = 0; nf < 4; nf++) {
                // b0: k = kbase + bq, b1: k = kbase + bq + 4, n = wn + nf*8 + bcol
                int ncol = wn + nf * 8 + bcol;
                bf[nf][0] = __float_as_uint(Bs[(kbase + bq) * LDB + ncol]);
                bf[nf][1] = __float_as_uint(Bs[(kbase + bq + 4) * LDB + ncol]);
            }
            #pragma unroll
            for (int mf = 0; mf < 4; mf++)
                #pragma unroll
                for (int nf = 0; nf < 4; nf++) {
                    asm volatile(
                        "mma.sync.aligned.m16n8k8.row.col.f32.tf32.tf32.f32 "
                        "{%0,%1,%2,%3}, {%4,%5,%6,%7}, {%8,%9}, {%0,%1,%2,%3};"
                        : "+f"(c[mf][nf][0]), "+f"(c[mf][nf][1]),
                          "+f"(c[mf][nf][2]), "+f"(c[mf][nf][3])
                        : "r"(af[mf][0]), "r"(af[mf][1]), "r"(af[mf][2]), "r"(af[mf][3]),
                          "r"(bf[nf][0]), "r"(bf[nf][1]));
                }
        }
        __syncthreads();
    }

    // epilogue
    #pragma unroll
    for (int mf = 0; mf < 4; mf++) {
        int row0 = bm + wm + mf * 16 + (lane >> 2);
        #pragma unroll
        for (int nf = 0; nf < 4; nf++) {
            int col = bn + wn + nf * 8 + (lane & 3) * 2;
            float bx = bias[col], by = bias[col + 1];
            float2 v0, v1;
            v0.x = c[mf][nf][0] + bx; v0.y = c[mf][nf][1] + by;
            v1.x = c[mf][nf][2] + bx; v1.y = c[mf][nf][3] + by;
            if (mode == 1) {
                v0.x = fmaxf(v0.x, 0.f); v0.y = fmaxf(v0.y, 0.f);
                v1.x = fmaxf(v1.x, 0.f); v1.y = fmaxf(v1.y, 0.f);
            }
            if (mode == 2) {
                __nv_bfloat16* C = (__nv_bfloat16*)Cv;
                if (row0 < M)
                    *reinterpret_cast<__nv_bfloat162*>(C + (size_t)row0 * N + col) =
                        __floats2bfloat162_rn(v0.x, v0.y);
                if (row0 + 8 < M)
                    *reinterpret_cast<__nv_bfloat162*>(C + (size_t)(row0 + 8) * N + col) =
                        __floats2bfloat162_rn(v1.x, v1.y);
            } else {
                float* C = (float*)Cv;
                if (row0 < M)
                    *reinterpret_cast<float2*>(C + (size_t)row0 * N + col) = v0;
                if (row0 + 8 < M)
                    *reinterpret_cast<float2*>(C + (size_t)(row0 + 8) * N + col) = v1;
            }
        }
    }
}

// ---------------- deformable sampling (bf16 value, half-warp per corner) ----
__global__ __launch_bounds__(256)
void sample_kernel(const __nv_bfloat16* __restrict__ valh,
                   const float* __restrict__ refp,
                   const float* __restrict__ off,
                   const float* __restrict__ lgt,
                   const int* __restrict__ shapes,
                   const int* __restrict__ starts,
                   float* __restrict__ acc) {
    __shared__ float aw_s[NH * 16];
    __shared__ int2  pw_s[512];

    int lq = blockIdx.x;
    int tid = threadIdx.x;
    int h = tid >> 5;
    int lane = tid & 31;
    const unsigned FULL = 0xffffffffu;

    {
        const float* lg = lgt + (size_t)lq * 128 + h * 16;
        float myl = (lane < 16) ? lg[lane] : -1e30f;
        float mx = myl;
        #pragma unroll
        for (int o = 8; o; o >>= 1) mx = fmaxf(mx, __shfl_xor_sync(FULL, mx, o));
        float e = (lane < 16) ? __expf(myl - mx) : 0.f;
        float sum = e;
        #pragma unroll
        for (int o = 16; o; o >>= 1) sum += __shfl_xor_sync(FULL, sum, o);
        float inv = 1.f / sum;
        if (lane < 16) aw_s[h * 16 + lane] = e * inv;
    }
    __syncthreads();

    #pragma unroll
    for (int rep = 0; rep < 2; rep++) {
        int j = tid + rep * 256;
        int jh = j >> 6;
        int rem = j & 63;
        int p = rem >> 2;
        int cc = rem & 3;
        int dx = cc & 1, dy = cc >> 1;
        int l = p >> 2;

        int Hl = __ldg(&shapes[l * 2 + 0]);
        int Wl = __ldg(&shapes[l * 2 + 1]);
        int st = __ldg(&starts[l]);
        float fW = (float)Wl, fH = (float)Hl;

        float rx = __ldg(&refp[(size_t)lq * 8 + l * 2 + 0]);
        float ry = __ldg(&refp[(size_t)lq * 8 + l * 2 + 1]);
        float ox = __ldg(&off[(size_t)lq * 256 + jh * 32 + p * 2 + 0]);
        float oy = __ldg(&off[(size_t)lq * 256 + jh * 32 + p * 2 + 1]);

        float x = rx * fW + ox - 0.5f;
        float y = ry * fH + oy - 0.5f;
        float x0f = floorf(x), y0f = floorf(y);
        float fx = x - x0f, fy = y - y0f;
        int xi = (int)x0f + dx;
        int yi = (int)y0f + dy;
        bool valid = ((unsigned)xi < (unsigned)Wl) & ((unsigned)yi < (unsigned)Hl);
        float wt = valid ? ((dx ? fx : 1.f - fx) * (dy ? fy : 1.f - fy)) * aw_s[jh * 16 + p]
                         : 0.f;
        int xc = min(max(xi, 0), Wl - 1);
        int yc = min(max(yi, 0), Hl - 1);
        int addr = (st + yc * Wl + xc) * 256 + jh * 32;
        pw_s[j] = make_int2(addr, __float_as_int(wt));
    }
    __syncthreads();

    {
        const int2* pw = pw_s + h * 64;
        int hw = lane >> 4;
        int sl = lane & 15;
        const __nv_bfloat162* vh = reinterpret_cast<const __nv_bfloat162*>(valh);
        float sx0 = 0.f, sy0 = 0.f, sx1 = 0.f, sy1 = 0.f;
        #pragma unroll
        for (int j0 = 0; j0 < 64; j0 += 8) {
            int2 q0 = pw[j0 + 0 + hw];
            int2 q1 = pw[j0 + 2 + hw];
            int2 q2 = pw[j0 + 4 + hw];
            int2 q3 = pw[j0 + 6 + hw];
            __nv_bfloat162 v0 = __ldg(vh + (q0.x >> 1) + sl);
            __nv_bfloat162 v1 = __ldg(vh + (q1.x >> 1) + sl);
            __nv_bfloat162 v2 = __ldg(vh + (q2.x >> 1) + sl);
            __nv_bfloat162 v3 = __ldg(vh + (q3.x >> 1) + sl);
            float w0 = __int_as_float(q0.y);
            float w1 = __int_as_float(q1.y);
            float w2 = __int_as_float(q2.y);
            float w3 = __int_as_float(q3.y);
            float2 f0 = __bfloat1622float2(v0);
            float2 f1 = __bfloat1622float2(v1);
            float2 f2 = __bfloat1622float2(v2);
            float2 f3 = __bfloat1622float2(v3);
            sx0 += w0 * f0.x; sy0 += w0 * f0.y;
            sx1 += w1 * f1.x; sy1 += w1 * f1.y;
            sx0 += w2 * f2.x; sy0 += w2 * f2.y;
            sx1 += w3 * f3.x; sy1 += w3 * f3.y;
        }
        float tx = sx0 + sx1;
        float ty = sy0 + sy1;
        tx += __shfl_xor_sync(FULL, tx, 16);
        ty += __shfl_xor_sync(FULL, ty, 16);
        if (lane < 16) {
            float2 o; o.x = tx; o.y = ty;
            *reinterpret_cast<float2*>(acc + (size_t)lq * 256 + h * 32 + 2 * sl) = o;
        }
    }
}

// ---------------- fused residual + LayerNorm (warp per row) ----------------
__global__ __launch_bounds__(256)
void ln_kernel(const float* __restrict__ res, const float* __restrict__ y,
               const float* __restrict__ g, const float* __restrict__ b,
               float* __restrict__ out, int M) {
    int warp = (blockIdx.x * blockDim.x + threadIdx.x) >> 5;
    int lane = threadIdx.x & 31;
    if (warp >= M) return;
    const float* r  = res + (size_t)warp * 256;
    const float* yy = y   + (size_t)warp * 256;
    float v[8];
    float s = 0.f;
    #pragma unroll
    for (int i = 0; i < 8; i++) {
        v[i] = r[lane + 32 * i] + yy[lane + 32 * i];
        s += v[i];
    }
    #pragma unroll
    for (int o = 16; o; o >>= 1) s += __shfl_xor_sync(0xffffffffu, s, o);
    float m = s * (1.f / 256.f);
    float vs = 0.f;
    #pragma unroll
    for (int i = 0; i < 8; i++) { float d = v[i] - m; vs += d * d; }
    #pragma unroll
    for (int o = 16; o; o >>= 1) vs += __shfl_xor_sync(0xffffffffu, vs, o);
    float rs = rsqrtf(vs * (1.f / 256.f) + 1e-5f);
    #pragma unroll
    for (int i = 0; i < 8; i++) {
        int c = lane + 32 * i;
        out[(size_t)warp * 256 + c] = (v[i] - m) * rs * g[c] + b[c];
    }
}

// ---------------- host ----------------
extern "C" void kernel_launch(void* const* d_in, const int* in_sizes, int n_in,
                              void* d_out, int out_size) {
    const float* query = (const float*)d_in[0];
    const float* refp  = (const float*)d_in[1];
    const float* pos   = (const float*)d_in[2];
    const int*   shp   = (const int*)d_in[3];
    const int*   sti   = (const int*)d_in[4];
    const float* w_off = (const float*)d_in[5];
    const float* b_off = (const float*)d_in[6];
    const float* w_attn= (const float*)d_in[7];
    const float* b_attn= (const float*)d_in[8];
    const float* w_val = (const float*)d_in[9];
    const float* b_val = (const float*)d_in[10];
    const float* w_out = (const float*)d_in[11];
    const float* b_out = (const float*)d_in[12];
    const float* g1    = (const float*)d_in[13];
    const float* be1   = (const float*)d_in[14];
    const float* w1    = (const float*)d_in[15];
    const float* b1    = (const float*)d_in[16];
    const float* w2    = (const float*)d_in[17];
    const float* b2    = (const float*)d_in[18];
    const float* g2    = (const float*)d_in[19];
    const float* be2   = (const float*)d_in[20];
    float* out = (float*)d_out;

    float *q, *off, *lgt, *acc, *x, *h, *f;
    __nv_bfloat16* valh;
    cudaGetSymbolAddress((void**)&q,   g_q);
    cudaGetSymbolAddress((void**)&valh,g_valh);
    cudaGetSymbolAddress((void**)&off, g_off);
    cudaGetSymbolAddress((void**)&lgt, g_lgt);
    cudaGetSymbolAddress((void**)&acc, g_acc);
    cudaGetSymbolAddress((void**)&x,   g_x);
    cudaGetSymbolAddress((void**)&h,   g_h);
    cudaGetSymbolAddress((void**)&f,   g_f);

    const int M = LQ;
    dim3 grid_n256(2, (M + 127) / 128);
    dim3 grid_n128(1, (M + 127) / 128);

    {
        int n4 = (LQ * D) / 4;
        add_kernel<<<(n4 + 255) / 256, 256>>>(query, pos, q, n4);
    }
    tgemm<<<grid_n256, 256>>>(query, w_val, b_val, valh, M, 256, 2);
    tgemm<<<grid_n256, 256>>>(q, w_off, b_off, off, M, 256, 0);
    tgemm<<<grid_n128, 256>>>(q, w_attn, b_attn, lgt, M, 128, 0);
    sample_kernel<<<LQ, 256>>>(valh, refp, off, lgt, shp, sti, acc);
    tgemm<<<grid_n256, 256>>>(acc, w_out, b_out, f, M, 256, 0);
    {
        int blocks = (M * 32 + 255) / 256;
        ln_kernel<<<blocks, 256>>>(query, f, g1, be1, x, M);
    }
    tgemm<<<grid_n256, 256>>>(x, w1, b1, h, M, 256, 1);
    tgemm<<<grid_n256, 256>>>(h, w2, b2, f, M, 256, 0);
    {
        int blocks = (M * 32 + 255) / 256;
        ln_kernel<<<blocks, 256>>>(x, f, g2, be2, out, M);
    }
}

// round 6
// speedup vs baseline: 3.7809x; 1.0290x over previous
#include <cuda_runtime.h>
#include <cuda_bf16.h>
#include <cstdint>

#define LQ 43054
#define D  256
#define NH 8
#define NL 4
#define NP 4
#define HD 32

// ---------------- scratch (device globals) ----------------
__device__ __nv_bfloat16 g_valh[LQ * D];
__device__ float g_off [LQ * 256];
__device__ float g_lgt [LQ * 128];
__device__ float g_acc [LQ * D];
__device__ float g_x   [LQ * D];
__device__ float g_h   [LQ * D];
__device__ float g_f   [LQ * D];

// ---------------- TF32 tensor-core GEMM ----------------
// C[M,N] = (A [+ A2])[M,256] @ B[256,N] + bias. BM=128, BN=128, BK=32.
// 256 threads = 8 warps (2x4); warp tile 64x32; mma.m16n8k8.tf32.
// mode: 0 = fp32 out, 1 = fp32+ReLU, 2 = bf16 out
__device__ __forceinline__ uint32_t cvt_tf32(float f) {
    uint32_t r;
    asm("cvt.rna.tf32.f32 %0, %1;" : "=r"(r) : "f"(f));
    return r;
}

__global__ __launch_bounds__(256, 2)
void tgemm(const float* __restrict__ A, const float* __restrict__ A2,
           const float* __restrict__ B,
           const float* __restrict__ bias, void* __restrict__ Cv,
           int M, int N, int mode) {
    constexpr int K = 256;
    constexpr int LDA = 36;
    constexpr int LDB = 132;
    __shared__ __align__(16) float As[128 * LDA];
    __shared__ __align__(16) float Bs[32 * LDB];

    int tid = threadIdx.x;
    int lane = tid & 31;
    int wid = tid >> 5;
    int bm = blockIdx.y * 128;
    int bn = blockIdx.x * 128;
    int wm = (wid >> 2) * 64;
    int wn = (wid & 3) * 32;

    float c[4][4][4];
    #pragma unroll
    for (int i = 0; i < 4; i++)
        #pragma unroll
        for (int j = 0; j < 4; j++)
            #pragma unroll
            for (int r = 0; r < 4; r++) c[i][j][r] = 0.f;

    int fr_row = (lane & 7) + ((lane & 8) ? 8 : 0);
    int fr_kad = (lane & 16) ? 4 : 0;
    int bq = lane & 3;
    int bcol = lane >> 2;

    for (int k0 = 0; k0 < K; k0 += 32) {
        #pragma unroll
        for (int i = 0; i < 4; i++) {
            int slot = tid + i * 256;
            int row = slot >> 3;
            int k4 = (slot & 7) * 4;
            float4 v = make_float4(0.f, 0.f, 0.f, 0.f);
            if (bm + row < M) {
                v = *reinterpret_cast<const float4*>(A + (size_t)(bm + row) * K + k0 + k4);
                if (A2) {
                    float4 u = *reinterpret_cast<const float4*>(A2 + (size_t)(bm + row) * K + k0 + k4);
                    v.x += u.x; v.y += u.y; v.z += u.z; v.w += u.w;
                }
            }
            uint4 t;
            t.x = cvt_tf32(v.x); t.y = cvt_tf32(v.y);
            t.z = cvt_tf32(v.z); t.w = cvt_tf32(v.w);
            *reinterpret_cast<uint4*>(&As[row * LDA + k4]) = t;
        }
        #pragma unroll
        for (int i = 0; i < 4; i++) {
            int slot = tid + i * 256;
            int kk = slot >> 5;
            int n4 = (slot & 31) * 4;
            float4 v = *reinterpret_cast<const float4*>(B + (size_t)(k0 + kk) * N + bn + n4);
            uint4 t;
            t.x = cvt_tf32(v.x); t.y = cvt_tf32(v.y);
            t.z = cvt_tf32(v.z); t.w = cvt_tf32(v.w);
            *reinterpret_cast<uint4*>(&Bs[kk * LDB + n4]) = t;
        }
        __syncthreads();

        #pragma unroll
        for (int k8 = 0; k8 < 4; k8++) {
            int kbase = k8 * 8;
            uint32_t af[4][4];
            #pragma unroll
            for (int mf = 0; mf < 4; mf++) {
                const float* p = &As[(wm + mf * 16 + fr_row) * LDA + kbase + fr_kad];
                uint32_t addr = (uint32_t)__cvta_generic_to_shared(p);
                asm volatile("ldmatrix.sync.aligned.m8n8.x4.shared.b16 {%0,%1,%2,%3}, [%4];"
                             : "=r"(af[mf][0]), "=r"(af[mf][1]), "=r"(af[mf][2]), "=r"(af[mf][3])
                             : "r"(addr));
            }
            uint32_t bf[4][2];
            #pragma unroll
            for (int nf = 0; nf < 4; nf++) {
                int ncol = wn + nf * 8 + bcol;
                bf[nf][0] = __float_as_uint(Bs[(kbase + bq) * LDB + ncol]);
                bf[nf][1] = __float_as_uint(Bs[(kbase + bq + 4) * LDB + ncol]);
            }
            #pragma unroll
            for (int mf = 0; mf < 4; mf++)
                #pragma unroll
                for (int nf = 0; nf < 4; nf++) {
                    asm volatile(
                        "mma.sync.aligned.m16n8k8.row.col.f32.tf32.tf32.f32 "
                        "{%0,%1,%2,%3}, {%4,%5,%6,%7}, {%8,%9}, {%0,%1,%2,%3};"
                        : "+f"(c[mf][nf][0]), "+f"(c[mf][nf][1]),
                          "+f"(c[mf][nf][2]), "+f"(c[mf][nf][3])
                        : "r"(af[mf][0]), "r"(af[mf][1]), "r"(af[mf][2]), "r"(af[mf][3]),
                          "r"(bf[nf][0]), "r"(bf[nf][1]));
                }
        }
        __syncthreads();
    }

    #pragma unroll
    for (int mf = 0; mf < 4; mf++) {
        int row0 = bm + wm + mf * 16 + (lane >> 2);
        #pragma unroll
        for (int nf = 0; nf < 4; nf++) {
            int col = bn + wn + nf * 8 + (lane & 3) * 2;
            float bx = bias[col], by = bias[col + 1];
            float2 v0, v1;
            v0.x = c[mf][nf][0] + bx; v0.y = c[mf][nf][1] + by;
            v1.x = c[mf][nf][2] + bx; v1.y = c[mf][nf][3] + by;
            if (mode == 1) {
                v0.x = fmaxf(v0.x, 0.f); v0.y = fmaxf(v0.y, 0.f);
                v1.x = fmaxf(v1.x, 0.f); v1.y = fmaxf(v1.y, 0.f);
            }
            if (mode == 2) {
                __nv_bfloat16* C = (__nv_bfloat16*)Cv;
                if (row0 < M)
                    *reinterpret_cast<__nv_bfloat162*>(C + (size_t)row0 * N + col) =
                        __floats2bfloat162_rn(v0.x, v0.y);
                if (row0 + 8 < M)
                    *reinterpret_cast<__nv_bfloat162*>(C + (size_t)(row0 + 8) * N + col) =
                        __floats2bfloat162_rn(v1.x, v1.y);
            } else {
                float* C = (float*)Cv;
                if (row0 < M)
                    *reinterpret_cast<float2*>(C + (size_t)row0 * N + col) = v0;
                if (row0 + 8 < M)
                    *reinterpret_cast<float2*>(C + (size_t)(row0 + 8) * N + col) = v1;
            }
        }
    }
}

// ---------------- deformable sampling (8 lanes per corner, 4 ch/lane) ----
__global__ __launch_bounds__(256)
void sample_kernel(const __nv_bfloat16* __restrict__ valh,
                   const float* __restrict__ refp,
                   const float* __restrict__ off,
                   const float* __restrict__ lgt,
                   const int* __restrict__ shapes,
                   const int* __restrict__ starts,
                   float* __restrict__ acc) {
    __shared__ float aw_s[NH * 16];
    __shared__ int2  pw_s[512];

    int lq = blockIdx.x;
    int tid = threadIdx.x;
    int h = tid >> 5;
    int lane = tid & 31;
    const unsigned FULL = 0xffffffffu;

    // phase 0: softmax per head
    {
        const float* lg = lgt + (size_t)lq * 128 + h * 16;
        float myl = (lane < 16) ? lg[lane] : -1e30f;
        float mx = myl;
        #pragma unroll
        for (int o = 8; o; o >>= 1) mx = fmaxf(mx, __shfl_xor_sync(FULL, mx, o));
        float e = (lane < 16) ? __expf(myl - mx) : 0.f;
        float sum = e;
        #pragma unroll
        for (int o = 16; o; o >>= 1) sum += __shfl_xor_sync(FULL, sum, o);
        float inv = 1.f / sum;
        if (lane < 16) aw_s[h * 16 + lane] = e * inv;
    }
    __syncthreads();

    // phase 1: 512 (addr, weight) pairs
    #pragma unroll
    for (int rep = 0; rep < 2; rep++) {
        int j = tid + rep * 256;
        int jh = j >> 6;
        int rem = j & 63;
        int p = rem >> 2;
        int cc = rem & 3;
        int dx = cc & 1, dy = cc >> 1;
        int l = p >> 2;

        int Hl = __ldg(&shapes[l * 2 + 0]);
        int Wl = __ldg(&shapes[l * 2 + 1]);
        int st = __ldg(&starts[l]);
        float fW = (float)Wl, fH = (float)Hl;

        float rx = __ldg(&refp[(size_t)lq * 8 + l * 2 + 0]);
        float ry = __ldg(&refp[(size_t)lq * 8 + l * 2 + 1]);
        float ox = __ldg(&off[(size_t)lq * 256 + jh * 32 + p * 2 + 0]);
        float oy = __ldg(&off[(size_t)lq * 256 + jh * 32 + p * 2 + 1]);

        float x = rx * fW + ox - 0.5f;
        float y = ry * fH + oy - 0.5f;
        float x0f = floorf(x), y0f = floorf(y);
        float fx = x - x0f, fy = y - y0f;
        int xi = (int)x0f + dx;
        int yi = (int)y0f + dy;
        bool valid = ((unsigned)xi < (unsigned)Wl) & ((unsigned)yi < (unsigned)Hl);
        float wt = valid ? ((dx ? fx : 1.f - fx) * (dy ? fy : 1.f - fy)) * aw_s[jh * 16 + p]
                         : 0.f;
        int xc = min(max(xi, 0), Wl - 1);
        int yc = min(max(yi, 0), Hl - 1);
        int addr = (st + yc * Wl + xc) * 256 + jh * 32;   // bf16 element index
        pw_s[j] = make_int2(addr, __float_as_int(wt));
    }
    __syncthreads();

    // phase 2: warp h, 4 corners per LDG.64, lane covers channels 4*(lane&7)..+3
    {
        const int2* pw = pw_s + h * 64;
        int cg = lane >> 3;            // corner subgroup 0..3
        int ch = lane & 7;             // channel quad
        float ax = 0.f, ay = 0.f, az = 0.f, aw = 0.f;
        #pragma unroll
        for (int j0 = 0; j0 < 64; j0 += 4) {
            int2 qq = pw[j0 + cg];
            float w = __int_as_float(qq.y);
            uint2 v = __ldg(reinterpret_cast<const uint2*>(valh + qq.x) + ch);
            float2 f0 = __bfloat1622float2(*reinterpret_cast<__nv_bfloat162*>(&v.x));
            float2 f1 = __bfloat1622float2(*reinterpret_cast<__nv_bfloat162*>(&v.y));
            ax += w * f0.x; ay += w * f0.y;
            az += w * f1.x; aw += w * f1.y;
        }
        // reduce across corner subgroups (lanes differing in bits 3,4)
        #pragma unroll
        for (int o = 8; o <= 16; o <<= 1) {
            ax += __shfl_xor_sync(FULL, ax, o);
            ay += __shfl_xor_sync(FULL, ay, o);
            az += __shfl_xor_sync(FULL, az, o);
            aw += __shfl_xor_sync(FULL, aw, o);
        }
        if (lane < 8) {
            float4 o4; o4.x = ax; o4.y = ay; o4.z = az; o4.w = aw;
            *reinterpret_cast<float4*>(acc + (size_t)lq * 256 + h * 32 + 4 * ch) = o4;
        }
    }
}

// ---------------- fused residual + LayerNorm (warp per row) ----------------
__global__ __launch_bounds__(256)
void ln_kernel(const float* __restrict__ res, const float* __restrict__ y,
               const float* __restrict__ g, const float* __restrict__ b,
               float* __restrict__ out, int M) {
    int warp = (blockIdx.x * blockDim.x + threadIdx.x) >> 5;
    int lane = threadIdx.x & 31;
    if (warp >= M) return;
    const float* r  = res + (size_t)warp * 256;
    const float* yy = y   + (size_t)warp * 256;
    float v[8];
    float s = 0.f;
    #pragma unroll
    for (int i = 0; i < 8; i++) {
        v[i] = r[lane + 32 * i] + yy[lane + 32 * i];
        s += v[i];
    }
    #pragma unroll
    for (int o = 16; o; o >>= 1) s += __shfl_xor_sync(0xffffffffu, s, o);
    float m = s * (1.f / 256.f);
    float vs = 0.f;
    #pragma unroll
    for (int i = 0; i < 8; i++) { float d = v[i] - m; vs += d * d; }
    #pragma unroll
    for (int o = 16; o; o >>= 1) vs += __shfl_xor_sync(0xffffffffu, vs, o);
    float rs = rsqrtf(vs * (1.f / 256.f) + 1e-5f);
    #pragma unroll
    for (int i = 0; i < 8; i++) {
        int c = lane + 32 * i;
        out[(size_t)warp * 256 + c] = (v[i] - m) * rs * g[c] + b[c];
    }
}

// ---------------- host ----------------
extern "C" void kernel_launch(void* const* d_in, const int* in_sizes, int n_in,
                              void* d_out, int out_size) {
    const float* query = (const float*)d_in[0];
    const float* refp  = (const float*)d_in[1];
    const float* pos   = (const float*)d_in[2];
    const int*   shp   = (const int*)d_in[3];
    const int*   sti   = (const int*)d_in[4];
    const float* w_off = (const float*)d_in[5];
    const float* b_off = (const float*)d_in[6];
    const float* w_attn= (const float*)d_in[7];
    const float* b_attn= (const float*)d_in[8];
    const float* w_val = (const float*)d_in[9];
    const float* b_val = (const float*)d_in[10];
    const float* w_out = (const float*)d_in[11];
    const float* b_out = (const float*)d_in[12];
    const float* g1    = (const float*)d_in[13];
    const float* be1   = (const float*)d_in[14];
    const float* w1    = (const float*)d_in[15];
    const float* b1    = (const float*)d_in[16];
    const float* w2    = (const float*)d_in[17];
    const float* b2    = (const float*)d_in[18];
    const float* g2    = (const float*)d_in[19];
    const float* be2   = (const float*)d_in[20];
    float* out = (float*)d_out;

    float *off, *lgt, *acc, *x, *h, *f;
    __nv_bfloat16* valh;
    cudaGetSymbolAddress((void**)&valh,g_valh);
    cudaGetSymbolAddress((void**)&off, g_off);
    cudaGetSymbolAddress((void**)&lgt, g_lgt);
    cudaGetSymbolAddress((void**)&acc, g_acc);
    cudaGetSymbolAddress((void**)&x,   g_x);
    cudaGetSymbolAddress((void**)&h,   g_h);
    cudaGetSymbolAddress((void**)&f,   g_f);

    const int M = LQ;
    dim3 grid_n256(2, (M + 127) / 128);
    dim3 grid_n128(1, (M + 127) / 128);

    tgemm<<<grid_n256, 256>>>(query, nullptr, w_val, b_val, valh, M, 256, 2);
    tgemm<<<grid_n256, 256>>>(query, pos, w_off, b_off, off, M, 256, 0);
    tgemm<<<grid_n128, 256>>>(query, pos, w_attn, b_attn, lgt, M, 128, 0);
    sample_kernel<<<LQ, 256>>>(valh, refp, off, lgt, shp, sti, acc);
    tgemm<<<grid_n256, 256>>>(acc, nullptr, w_out, b_out, f, M, 256, 0);
    {
        int blocks = (M * 32 + 255) / 256;
        ln_kernel<<<blocks, 256>>>(query, f, g1, be1, x, M);
    }
    tgemm<<<grid_n256, 256>>>(x, nullptr, w1, b1, h, M, 256, 1);
    tgemm<<<grid_n256, 256>>>(h, nullptr, w2, b2, f, M, 256, 0);
    {
        int blocks = (M * 32 + 255) / 256;
        ln_kernel<<<blocks, 256>>>(x, f, g2, be2, out, M);
    }
}

// round 7
// speedup vs baseline: 4.1532x; 1.0984x over previous
#include <cuda_runtime.h>
#include <cuda_bf16.h>
#include <cstdint>

#define LQ 43054
#define D  256
#define NH 8
#define NL 4
#define NP 4
#define HD 32

// ---------------- scratch (device globals) ----------------
__device__ __nv_bfloat16 g_valh[LQ * D];
__device__ float g_ol  [LQ * 384];       // [0:256)=offsets, [256:384)=logits
__device__ float g_acc [LQ * D];
__device__ float g_x   [LQ * D];
__device__ float g_h   [LQ * D];
__device__ float g_f   [LQ * D];
__device__ float g_wcat[256 * 384];
__device__ float g_bcat[384];

// ---------------- weight pack: [w_off | w_attn] ----------------
__global__ void pack_w(const float* __restrict__ w_off, const float* __restrict__ b_off,
                       const float* __restrict__ w_attn, const float* __restrict__ b_attn,
                       float* __restrict__ wcat, float* __restrict__ bcat) {
    int i = blockIdx.x * blockDim.x + threadIdx.x;
    if (i >= 256 * 384) return;
    int k = i / 384, n = i % 384;
    wcat[i] = (n < 256) ? w_off[k * 256 + n] : w_attn[k * 128 + (n - 256)];
    if (i < 384) bcat[i] = (i < 256) ? b_off[i] : b_attn[i - 256];
}

// ---------------- TF32 tensor-core GEMM ----------------
__device__ __forceinline__ uint32_t cvt_tf32(float f) {
    uint32_t r;
    asm("cvt.rna.tf32.f32 %0, %1;" : "=r"(r) : "f"(f));
    return r;
}

__global__ __launch_bounds__(256, 2)
void tgemm(const float* __restrict__ A, const float* __restrict__ A2,
           const float* __restrict__ B,
           const float* __restrict__ bias, void* __restrict__ Cv,
           int M, int N, int mode) {
    constexpr int K = 256;
    constexpr int LDA = 36;
    constexpr int LDB = 132;
    __shared__ __align__(16) float As[128 * LDA];
    __shared__ __align__(16) float Bs[32 * LDB];

    int tid = threadIdx.x;
    int lane = tid & 31;
    int wid = tid >> 5;
    int bm = blockIdx.y * 128;
    int bn = blockIdx.x * 128;
    int wm = (wid >> 2) * 64;
    int wn = (wid & 3) * 32;

    float c[4][4][4];
    #pragma unroll
    for (int i = 0; i < 4; i++)
        #pragma unroll
        for (int j = 0; j < 4; j++)
            #pragma unroll
            for (int r = 0; r < 4; r++) c[i][j][r] = 0.f;

    int fr_row = (lane & 7) + ((lane & 8) ? 8 : 0);
    int fr_kad = (lane & 16) ? 4 : 0;
    int bq = lane & 3;
    int bcol = lane >> 2;

    for (int k0 = 0; k0 < K; k0 += 32) {
        #pragma unroll
        for (int i = 0; i < 4; i++) {
            int slot = tid + i * 256;
            int row = slot >> 3;
            int k4 = (slot & 7) * 4;
            float4 v = make_float4(0.f, 0.f, 0.f, 0.f);
            if (bm + row < M) {
                v = *reinterpret_cast<const float4*>(A + (size_t)(bm + row) * K + k0 + k4);
                if (A2) {
                    float4 u = *reinterpret_cast<const float4*>(A2 + (size_t)(bm + row) * K + k0 + k4);
                    v.x += u.x; v.y += u.y; v.z += u.z; v.w += u.w;
                }
            }
            uint4 t;
            t.x = cvt_tf32(v.x); t.y = cvt_tf32(v.y);
            t.z = cvt_tf32(v.z); t.w = cvt_tf32(v.w);
            *reinterpret_cast<uint4*>(&As[row * LDA + k4]) = t;
        }
        #pragma unroll
        for (int i = 0; i < 4; i++) {
            int slot = tid + i * 256;
            int kk = slot >> 5;
            int n4 = (slot & 31) * 4;
            float4 v = *reinterpret_cast<const float4*>(B + (size_t)(k0 + kk) * N + bn + n4);
            uint4 t;
            t.x = cvt_tf32(v.x); t.y = cvt_tf32(v.y);
            t.z = cvt_tf32(v.z); t.w = cvt_tf32(v.w);
            *reinterpret_cast<uint4*>(&Bs[kk * LDB + n4]) = t;
        }
        __syncthreads();

        #pragma unroll
        for (int k8 = 0; k8 < 4; k8++) {
            int kbase = k8 * 8;
            uint32_t af[4][4];
            #pragma unroll
            for (int mf = 0; mf < 4; mf++) {
                const float* p = &As[(wm + mf * 16 + fr_row) * LDA + kbase + fr_kad];
                uint32_t addr = (uint32_t)__cvta_generic_to_shared(p);
                asm volatile("ldmatrix.sync.aligned.m8n8.x4.shared.b16 {%0,%1,%2,%3}, [%4];"
                             : "=r"(af[mf][0]), "=r"(af[mf][1]), "=r"(af[mf][2]), "=r"(af[mf][3])
                             : "r"(addr));
            }
            uint32_t bf[4][2];
            #pragma unroll
            for (int nf = 0; nf < 4; nf++) {
                int ncol = wn + nf * 8 + bcol;
                bf[nf][0] = __float_as_uint(Bs[(kbase + bq) * LDB + ncol]);
                bf[nf][1] = __float_as_uint(Bs[(kbase + bq + 4) * LDB + ncol]);
            }
            #pragma unroll
            for (int mf = 0; mf < 4; mf++)
                #pragma unroll
                for (int nf = 0; nf < 4; nf++) {
                    asm volatile(
                        "mma.sync.aligned.m16n8k8.row.col.f32.tf32.tf32.f32 "
                        "{%0,%1,%2,%3}, {%4,%5,%6,%7}, {%8,%9}, {%0,%1,%2,%3};"
                        : "+f"(c[mf][nf][0]), "+f"(c[mf][nf][1]),
                          "+f"(c[mf][nf][2]), "+f"(c[mf][nf][3])
                        : "r"(af[mf][0]), "r"(af[mf][1]), "r"(af[mf][2]), "r"(af[mf][3]),
                          "r"(bf[nf][0]), "r"(bf[nf][1]));
                }
        }
        __syncthreads();
    }

    #pragma unroll
    for (int mf = 0; mf < 4; mf++) {
        int row0 = bm + wm + mf * 16 + (lane >> 2);
        #pragma unroll
        for (int nf = 0; nf < 4; nf++) {
            int col = bn + wn + nf * 8 + (lane & 3) * 2;
            float bx = bias[col], by = bias[col + 1];
            float2 v0, v1;
            v0.x = c[mf][nf][0] + bx; v0.y = c[mf][nf][1] + by;
            v1.x = c[mf][nf][2] + bx; v1.y = c[mf][nf][3] + by;
            if (mode == 1) {
                v0.x = fmaxf(v0.x, 0.f); v0.y = fmaxf(v0.y, 0.f);
                v1.x = fmaxf(v1.x, 0.f); v1.y = fmaxf(v1.y, 0.f);
            }
            if (mode == 2) {
                __nv_bfloat16* C = (__nv_bfloat16*)Cv;
                if (row0 < M)
                    *reinterpret_cast<__nv_bfloat162*>(C + (size_t)row0 * N + col) =
                        __floats2bfloat162_rn(v0.x, v0.y);
                if (row0 + 8 < M)
                    *reinterpret_cast<__nv_bfloat162*>(C + (size_t)(row0 + 8) * N + col) =
                        __floats2bfloat162_rn(v1.x, v1.y);
            } else {
                float* C = (float*)Cv;
                if (row0 < M)
                    *reinterpret_cast<float2*>(C + (size_t)row0 * N + col) = v0;
                if (row0 + 8 < M)
                    *reinterpret_cast<float2*>(C + (size_t)(row0 + 8) * N + col) = v1;
            }
        }
    }
}

// ---------------- deformable sampling (LDG.128: 4 lanes/corner) ----------
__global__ __launch_bounds__(256)
void sample_kernel(const __nv_bfloat16* __restrict__ valh,
                   const float* __restrict__ refp,
                   const float* __restrict__ ol,     // (LQ, 384): off | logits
                   const int* __restrict__ shapes,
                   const int* __restrict__ starts,
                   float* __restrict__ acc) {
    __shared__ float aw_s[NH * 16];
    __shared__ int2  pw_s[512];

    int lq = blockIdx.x;
    int tid = threadIdx.x;
    int h = tid >> 5;
    int lane = tid & 31;
    const unsigned FULL = 0xffffffffu;

    // phase 0: softmax per head (logits at ol[lq*384 + 256 + h*16])
    {
        const float* lg = ol + (size_t)lq * 384 + 256 + h * 16;
        float myl = (lane < 16) ? lg[lane] : -1e30f;
        float mx = myl;
        #pragma unroll
        for (int o = 8; o; o >>= 1) mx = fmaxf(mx, __shfl_xor_sync(FULL, mx, o));
        float e = (lane < 16) ? __expf(myl - mx) : 0.f;
        float sum = e;
        #pragma unroll
        for (int o = 16; o; o >>= 1) sum += __shfl_xor_sync(FULL, sum, o);
        float inv = 1.f / sum;
        if (lane < 16) aw_s[h * 16 + lane] = e * inv;
    }
    __syncthreads();

    // phase 1: 512 (byte-addr, weight) pairs
    #pragma unroll
    for (int rep = 0; rep < 2; rep++) {
        int j = tid + rep * 256;
        int jh = j >> 6;
        int rem = j & 63;
        int p = rem >> 2;
        int cc = rem & 3;
        int dx = cc & 1, dy = cc >> 1;
        int l = p >> 2;

        int Hl = __ldg(&shapes[l * 2 + 0]);
        int Wl = __ldg(&shapes[l * 2 + 1]);
        int st = __ldg(&starts[l]);
        float fW = (float)Wl, fH = (float)Hl;

        float rx = __ldg(&refp[(size_t)lq * 8 + l * 2 + 0]);
        float ry = __ldg(&refp[(size_t)lq * 8 + l * 2 + 1]);
        float ox = __ldg(&ol[(size_t)lq * 384 + jh * 32 + p * 2 + 0]);
        float oy = __ldg(&ol[(size_t)lq * 384 + jh * 32 + p * 2 + 1]);

        float x = rx * fW + ox - 0.5f;
        float y = ry * fH + oy - 0.5f;
        float x0f = floorf(x), y0f = floorf(y);
        float fx = x - x0f, fy = y - y0f;
        int xi = (int)x0f + dx;
        int yi = (int)y0f + dy;
        bool valid = ((unsigned)xi < (unsigned)Wl) & ((unsigned)yi < (unsigned)Hl);
        float wt = valid ? ((dx ? fx : 1.f - fx) * (dy ? fy : 1.f - fy)) * aw_s[jh * 16 + p]
                         : 0.f;
        int xc = min(max(xi, 0), Wl - 1);
        int yc = min(max(yi, 0), Hl - 1);
        int addr = ((st + yc * Wl + xc) * 256 + jh * 32) * 2;   // byte offset
        pw_s[j] = make_int2(addr, __float_as_int(wt));
    }
    __syncthreads();

    // phase 2: 8 corners per LDG.128 round; lane = corner(bits 2-4) x chunk(bits 0-1)
    {
        const int2* pw = pw_s + h * 64;
        int cor = lane >> 2;           // 0..7
        int ch = lane & 3;             // 16B chunk -> channels 8ch..8ch+7
        const char* vbase = reinterpret_cast<const char*>(valh) + 16 * ch;
        float a[8];
        #pragma unroll
        for (int i = 0; i < 8; i++) a[i] = 0.f;
        #pragma unroll
        for (int j0 = 0; j0 < 64; j0 += 8) {
            int2 qq = pw[j0 + cor];
            float w = __int_as_float(qq.y);
            uint4 v = *reinterpret_cast<const uint4*>(vbase + qq.x);
            float2 f0 = __bfloat1622float2(*reinterpret_cast<__nv_bfloat162*>(&v.x));
            float2 f1 = __bfloat1622float2(*reinterpret_cast<__nv_bfloat162*>(&v.y));
            float2 f2 = __bfloat1622float2(*reinterpret_cast<__nv_bfloat162*>(&v.z));
            float2 f3 = __bfloat1622float2(*reinterpret_cast<__nv_bfloat162*>(&v.w));
            a[0] += w * f0.x; a[1] += w * f0.y;
            a[2] += w * f1.x; a[3] += w * f1.y;
            a[4] += w * f2.x; a[5] += w * f2.y;
            a[6] += w * f3.x; a[7] += w * f3.y;
        }
        // reduce over corner bits (2,3,4)
        #pragma unroll
        for (int o = 4; o <= 16; o <<= 1)
            #pragma unroll
            for (int i = 0; i < 8; i++)
                a[i] += __shfl_xor_sync(FULL, a[i], o);
        if (lane < 4) {
            float* dst = acc + (size_t)lq * 256 + h * 32 + 8 * ch;
            float4 o0; o0.x = a[0]; o0.y = a[1]; o0.z = a[2]; o0.w = a[3];
            float4 o1; o1.x = a[4]; o1.y = a[5]; o1.z = a[6]; o1.w = a[7];
            *reinterpret_cast<float4*>(dst) = o0;
            *reinterpret_cast<float4*>(dst + 4) = o1;
        }
    }
}

// ---------------- fused residual + LayerNorm (warp per row) ----------------
__global__ __launch_bounds__(256)
void ln_kernel(const float* __restrict__ res, const float* __restrict__ y,
               const float* __restrict__ g, const float* __restrict__ b,
               float* __restrict__ out, int M) {
    int warp = (blockIdx.x * blockDim.x + threadIdx.x) >> 5;
    int lane = threadIdx.x & 31;
    if (warp >= M) return;
    const float* r  = res + (size_t)warp * 256;
    const float* yy = y   + (size_t)warp * 256;
    float v[8];
    float s = 0.f;
    #pragma unroll
    for (int i = 0; i < 8; i++) {
        v[i] = r[lane + 32 * i] + yy[lane + 32 * i];
        s += v[i];
    }
    #pragma unroll
    for (int o = 16; o; o >>= 1) s += __shfl_xor_sync(0xffffffffu, s, o);
    float m = s * (1.f / 256.f);
    float vs = 0.f;
    #pragma unroll
    for (int i = 0; i < 8; i++) { float d = v[i] - m; vs += d * d; }
    #pragma unroll
    for (int o = 16; o; o >>= 1) vs += __shfl_xor_sync(0xffffffffu, vs, o);
    float rs = rsqrtf(vs * (1.f / 256.f) + 1e-5f);
    #pragma unroll
    for (int i = 0; i < 8; i++) {
        int c = lane + 32 * i;
        out[(size_t)warp * 256 + c] = (v[i] - m) * rs * g[c] + b[c];
    }
}

// ---------------- host ----------------
extern "C" void kernel_launch(void* const* d_in, const int* in_sizes, int n_in,
                              void* d_out, int out_size) {
    const float* query = (const float*)d_in[0];
    const float* refp  = (const float*)d_in[1];
    const float* pos   = (const float*)d_in[2];
    const int*   shp   = (const int*)d_in[3];
    const int*   sti   = (const int*)d_in[4];
    const float* w_off = (const float*)d_in[5];
    const float* b_off = (const float*)d_in[6];
    const float* w_attn= (const float*)d_in[7];
    const float* b_attn= (const float*)d_in[8];
    const float* w_val = (const float*)d_in[9];
    const float* b_val = (const float*)d_in[10];
    const float* w_out = (const float*)d_in[11];
    const float* b_out = (const float*)d_in[12];
    const float* g1    = (const float*)d_in[13];
    const float* be1   = (const float*)d_in[14];
    const float* w1    = (const float*)d_in[15];
    const float* b1    = (const float*)d_in[16];
    const float* w2    = (const float*)d_in[17];
    const float* b2    = (const float*)d_in[18];
    const float* g2    = (const float*)d_in[19];
    const float* be2   = (const float*)d_in[20];
    float* out = (float*)d_out;

    float *ol, *acc, *x, *h, *f, *wcat, *bcat;
    __nv_bfloat16* valh;
    cudaGetSymbolAddress((void**)&valh, g_valh);
    cudaGetSymbolAddress((void**)&ol,   g_ol);
    cudaGetSymbolAddress((void**)&acc,  g_acc);
    cudaGetSymbolAddress((void**)&x,    g_x);
    cudaGetSymbolAddress((void**)&h,    g_h);
    cudaGetSymbolAddress((void**)&f,    g_f);
    cudaGetSymbolAddress((void**)&wcat, g_wcat);
    cudaGetSymbolAddress((void**)&bcat, g_bcat);

    const int M = LQ;
    dim3 grid_n256(2, (M + 127) / 128);
    dim3 grid_n384(3, (M + 127) / 128);

    // fork: value GEMM on side stream, pack+merged GEMM on main stream
    cudaStream_t s1;
    cudaStreamCreateWithFlags(&s1, cudaStreamNonBlocking);
    cudaEvent_t e0, e1;
    cudaEventCreateWithFlags(&e0, cudaEventDisableTiming);
    cudaEventCreateWithFlags(&e1, cudaEventDisableTiming);

    cudaEventRecord(e0, 0);
    cudaStreamWaitEvent(s1, e0, 0);
    tgemm<<<grid_n256, 256, 0, s1>>>(query, nullptr, w_val, b_val, valh, M, 256, 2);

    pack_w<<<(256 * 384 + 255) / 256, 256>>>(w_off, b_off, w_attn, b_attn, wcat, bcat);
    tgemm<<<grid_n384, 256>>>(query, pos, wcat, bcat, ol, M, 384, 0);

    cudaEventRecord(e1, s1);
    cudaStreamWaitEvent(0, e1, 0);

    sample_kernel<<<LQ, 256>>>(valh, refp, ol, shp, sti, acc);
    tgemm<<<grid_n256, 256>>>(acc, nullptr, w_out, b_out, f, M, 256, 0);
    {
        int blocks = (M * 32 + 255) / 256;
        ln_kernel<<<blocks, 256>>>(query, f, g1, be1, x, M);
    }
    tgemm<<<grid_n256, 256>>>(x, nullptr, w1, b1, h, M, 256, 1);
    tgemm<<<grid_n256, 256>>>(h, nullptr, w2, b2, f, M, 256, 0);
    {
        int blocks = (M * 32 + 255) / 256;
        ln_kernel<<<blocks, 256>>>(x, f, g2, be2, out, M);
    }
}

// round 8
// speedup vs baseline: 4.2671x; 1.0274x over previous
#include <cuda_runtime.h>
#include <cuda_bf16.h>
#include <cstdint>

#define LQ 43054
#define D  256
#define NH 8
#define NL 4
#define NP 4
#define HD 32

// ---------------- scratch (device globals) ----------------
__device__ __nv_bfloat16 g_valh[LQ * D];
__device__ float g_ol  [LQ * 384];       // [0:256)=offsets, [256:384)=logits
__device__ float g_acc [LQ * D];
__device__ float g_x   [LQ * D];
__device__ float g_h   [LQ * D];
__device__ float g_f   [LQ * D];
__device__ float g_wcat[256 * 384];
__device__ float g_bcat[384];

// ---------------- weight pack: [w_off | w_attn] ----------------
__global__ void pack_w(const float* __restrict__ w_off, const float* __restrict__ b_off,
                       const float* __restrict__ w_attn, const float* __restrict__ b_attn,
                       float* __restrict__ wcat, float* __restrict__ bcat) {
    int i = blockIdx.x * blockDim.x + threadIdx.x;
    if (i >= 256 * 384) return;
    int k = i / 384, n = i % 384;
    wcat[i] = (n < 256) ? w_off[k * 256 + n] : w_attn[k * 128 + (n - 256)];
    if (i < 384) bcat[i] = (i < 256) ? b_off[i] : b_attn[i - 256];
}

// ---------------- bf16 tensor-core GEMM ----------------
// C[M,N] = (A [+ A2])[M,256] @ B[256,N] + bias. BM=128, BN=128, BK=64.
// 256 threads = 8 warps (2x4); warp tile 64x32; mma.m16n8k16.bf16, fp32 accum.
// mode: 0 = fp32 out, 1 = fp32+ReLU, 2 = bf16 out
__global__ __launch_bounds__(256, 2)
void tgemm(const float* __restrict__ A, const float* __restrict__ A2,
           const float* __restrict__ B,
           const float* __restrict__ bias, void* __restrict__ Cv,
           int M, int N, int mode) {
    constexpr int K = 256;
    constexpr int LDA = 72;    // bf16 elems per A row (64 + 8 pad)   -> 144 B
    constexpr int LDB = 136;   // bf16 elems per B row (128 + 8 pad)  -> 272 B
    __shared__ __align__(16) __nv_bfloat16 As[128 * LDA];
    __shared__ __align__(16) __nv_bfloat16 Bs[64 * LDB];

    int tid = threadIdx.x;
    int lane = tid & 31;
    int wid = tid >> 5;
    int bm = blockIdx.y * 128;
    int bn = blockIdx.x * 128;
    int wm = (wid >> 2) * 64;
    int wn = (wid & 3) * 32;

    float c[4][4][4];
    #pragma unroll
    for (int i = 0; i < 4; i++)
        #pragma unroll
        for (int j = 0; j < 4; j++)
            #pragma unroll
            for (int r = 0; r < 4; r++) c[i][j][r] = 0.f;

    // ldmatrix lane addressing
    int a_row = lane & 15;                 // m within 16
    int a_koff = (lane >> 4) * 8;          // 0 / 8
    int b_krow = (lane & 7) + ((lane >> 3) & 1) * 8;  // k within 16
    int b_noff = (lane >> 4) * 8;          // 0 / 8

    for (int k0 = 0; k0 < K; k0 += 64) {
        // stage A: 128 rows x 64 k (f32 -> bf16); 2048 float4 loads
        #pragma unroll
        for (int i = 0; i < 8; i++) {
            int slot = tid + i * 256;
            int row = slot >> 4;
            int k4 = (slot & 15) * 4;
            float4 v = make_float4(0.f, 0.f, 0.f, 0.f);
            if (bm + row < M) {
                v = *reinterpret_cast<const float4*>(A + (size_t)(bm + row) * K + k0 + k4);
                if (A2) {
                    float4 u = *reinterpret_cast<const float4*>(A2 + (size_t)(bm + row) * K + k0 + k4);
                    v.x += u.x; v.y += u.y; v.z += u.z; v.w += u.w;
                }
            }
            __nv_bfloat162 p0 = __floats2bfloat162_rn(v.x, v.y);
            __nv_bfloat162 p1 = __floats2bfloat162_rn(v.z, v.w);
            uint2 st;
            st.x = *reinterpret_cast<uint32_t*>(&p0);
            st.y = *reinterpret_cast<uint32_t*>(&p1);
            *reinterpret_cast<uint2*>(&As[row * LDA + k4]) = st;
        }
        // stage B: 64 k-rows x 128 n (f32 -> bf16)
        #pragma unroll
        for (int i = 0; i < 8; i++) {
            int slot = tid + i * 256;
            int kk = slot >> 5;
            int n4 = (slot & 31) * 4;
            float4 v = *reinterpret_cast<const float4*>(B + (size_t)(k0 + kk) * N + bn + n4);
            __nv_bfloat162 p0 = __floats2bfloat162_rn(v.x, v.y);
            __nv_bfloat162 p1 = __floats2bfloat162_rn(v.z, v.w);
            uint2 st;
            st.x = *reinterpret_cast<uint32_t*>(&p0);
            st.y = *reinterpret_cast<uint32_t*>(&p1);
            *reinterpret_cast<uint2*>(&Bs[kk * LDB + n4]) = st;
        }
        __syncthreads();

        #pragma unroll
        for (int ks = 0; ks < 4; ks++) {
            int kbase = ks * 16;
            uint32_t af[4][4];
            #pragma unroll
            for (int mf = 0; mf < 4; mf++) {
                const __nv_bfloat16* p = &As[(wm + mf * 16 + a_row) * LDA + kbase + a_koff];
                uint32_t addr = (uint32_t)__cvta_generic_to_shared(p);
                asm volatile("ldmatrix.sync.aligned.m8n8.x4.shared.b16 {%0,%1,%2,%3}, [%4];"
                             : "=r"(af[mf][0]), "=r"(af[mf][1]), "=r"(af[mf][2]), "=r"(af[mf][3])
                             : "r"(addr));
            }
            uint32_t bf[4][2];
            #pragma unroll
            for (int n16 = 0; n16 < 2; n16++) {
                const __nv_bfloat16* p = &Bs[(kbase + b_krow) * LDB + wn + n16 * 16 + b_noff];
                uint32_t addr = (uint32_t)__cvta_generic_to_shared(p);
                asm volatile("ldmatrix.sync.aligned.m8n8.x4.trans.shared.b16 {%0,%1,%2,%3}, [%4];"
                             : "=r"(bf[n16 * 2][0]), "=r"(bf[n16 * 2][1]),
                               "=r"(bf[n16 * 2 + 1][0]), "=r"(bf[n16 * 2 + 1][1])
                             : "r"(addr));
            }
            #pragma unroll
            for (int mf = 0; mf < 4; mf++)
                #pragma unroll
                for (int nf = 0; nf < 4; nf++) {
                    asm volatile(
                        "mma.sync.aligned.m16n8k16.row.col.f32.bf16.bf16.f32 "
                        "{%0,%1,%2,%3}, {%4,%5,%6,%7}, {%8,%9}, {%0,%1,%2,%3};"
                        : "+f"(c[mf][nf][0]), "+f"(c[mf][nf][1]),
                          "+f"(c[mf][nf][2]), "+f"(c[mf][nf][3])
                        : "r"(af[mf][0]), "r"(af[mf][1]), "r"(af[mf][2]), "r"(af[mf][3]),
                          "r"(bf[nf][0]), "r"(bf[nf][1]));
                }
        }
        __syncthreads();
    }

    #pragma unroll
    for (int mf = 0; mf < 4; mf++) {
        int row0 = bm + wm + mf * 16 + (lane >> 2);
        #pragma unroll
        for (int nf = 0; nf < 4; nf++) {
            int col = bn + wn + nf * 8 + (lane & 3) * 2;
            float bx = bias[col], by = bias[col + 1];
            float2 v0, v1;
            v0.x = c[mf][nf][0] + bx; v0.y = c[mf][nf][1] + by;
            v1.x = c[mf][nf][2] + bx; v1.y = c[mf][nf][3] + by;
            if (mode == 1) {
                v0.x = fmaxf(v0.x, 0.f); v0.y = fmaxf(v0.y, 0.f);
                v1.x = fmaxf(v1.x, 0.f); v1.y = fmaxf(v1.y, 0.f);
            }
            if (mode == 2) {
                __nv_bfloat16* C = (__nv_bfloat16*)Cv;
                if (row0 < M)
                    *reinterpret_cast<__nv_bfloat162*>(C + (size_t)row0 * N + col) =
                        __floats2bfloat162_rn(v0.x, v0.y);
                if (row0 + 8 < M)
                    *reinterpret_cast<__nv_bfloat162*>(C + (size_t)(row0 + 8) * N + col) =
                        __floats2bfloat162_rn(v1.x, v1.y);
            } else {
                float* C = (float*)Cv;
                if (row0 < M)
                    *reinterpret_cast<float2*>(C + (size_t)row0 * N + col) = v0;
                if (row0 + 8 < M)
                    *reinterpret_cast<float2*>(C + (size_t)(row0 + 8) * N + col) = v1;
            }
        }
    }
}

// ---------------- deformable sampling (LDG.128: 4 lanes/corner) ----------
__global__ __launch_bounds__(256)
void sample_kernel(const __nv_bfloat16* __restrict__ valh,
                   const float* __restrict__ refp,
                   const float* __restrict__ ol,     // (LQ, 384): off | logits
                   const int* __restrict__ shapes,
                   const int* __restrict__ starts,
                   float* __restrict__ acc) {
    __shared__ float aw_s[NH * 16];
    __shared__ int2  pw_s[512];

    int lq = blockIdx.x;
    int tid = threadIdx.x;
    int h = tid >> 5;
    int lane = tid & 31;
    const unsigned FULL = 0xffffffffu;

    {
        const float* lg = ol + (size_t)lq * 384 + 256 + h * 16;
        float myl = (lane < 16) ? lg[lane] : -1e30f;
        float mx = myl;
        #pragma unroll
        for (int o = 8; o; o >>= 1) mx = fmaxf(mx, __shfl_xor_sync(FULL, mx, o));
        float e = (lane < 16) ? __expf(myl - mx) : 0.f;
        float sum = e;
        #pragma unroll
        for (int o = 16; o; o >>= 1) sum += __shfl_xor_sync(FULL, sum, o);
        float inv = 1.f / sum;
        if (lane < 16) aw_s[h * 16 + lane] = e * inv;
    }
    __syncthreads();

    #pragma unroll
    for (int rep = 0; rep < 2; rep++) {
        int j = tid + rep * 256;
        int jh = j >> 6;
        int rem = j & 63;
        int p = rem >> 2;
        int cc = rem & 3;
        int dx = cc & 1, dy = cc >> 1;
        int l = p >> 2;

        int Hl = __ldg(&shapes[l * 2 + 0]);
        int Wl = __ldg(&shapes[l * 2 + 1]);
        int st = __ldg(&starts[l]);
        float fW = (float)Wl, fH = (float)Hl;

        float rx = __ldg(&refp[(size_t)lq * 8 + l * 2 + 0]);
        float ry = __ldg(&refp[(size_t)lq * 8 + l * 2 + 1]);
        float ox = __ldg(&ol[(size_t)lq * 384 + jh * 32 + p * 2 + 0]);
        float oy = __ldg(&ol[(size_t)lq * 384 + jh * 32 + p * 2 + 1]);

        float x = rx * fW + ox - 0.5f;
        float y = ry * fH + oy - 0.5f;
        float x0f = floorf(x), y0f = floorf(y);
        float fx = x - x0f, fy = y - y0f;
        int xi = (int)x0f + dx;
        int yi = (int)y0f + dy;
        bool valid = ((unsigned)xi < (unsigned)Wl) & ((unsigned)yi < (unsigned)Hl);
        float wt = valid ? ((dx ? fx : 1.f - fx) * (dy ? fy : 1.f - fy)) * aw_s[jh * 16 + p]
                         : 0.f;
        int xc = min(max(xi, 0), Wl - 1);
        int yc = min(max(yi, 0), Hl - 1);
        int addr = ((st + yc * Wl + xc) * 256 + jh * 32) * 2;   // byte offset
        pw_s[j] = make_int2(addr, __float_as_int(wt));
    }
    __syncthreads();

    {
        const int2* pw = pw_s + h * 64;
        int cor = lane >> 2;
        int ch = lane & 3;
        const char* vbase = reinterpret_cast<const char*>(valh) + 16 * ch;
        float a[8];
        #pragma unroll
        for (int i = 0; i < 8; i++) a[i] = 0.f;
        #pragma unroll
        for (int j0 = 0; j0 < 64; j0 += 8) {
            int2 qq = pw[j0 + cor];
            float w = __int_as_float(qq.y);
            uint4 v = *reinterpret_cast<const uint4*>(vbase + qq.x);
            float2 f0 = __bfloat1622float2(*reinterpret_cast<__nv_bfloat162*>(&v.x));
            float2 f1 = __bfloat1622float2(*reinterpret_cast<__nv_bfloat162*>(&v.y));
            float2 f2 = __bfloat1622float2(*reinterpret_cast<__nv_bfloat162*>(&v.z));
            float2 f3 = __bfloat1622float2(*reinterpret_cast<__nv_bfloat162*>(&v.w));
            a[0] += w * f0.x; a[1] += w * f0.y;
            a[2] += w * f1.x; a[3] += w * f1.y;
            a[4] += w * f2.x; a[5] += w * f2.y;
            a[6] += w * f3.x; a[7] += w * f3.y;
        }
        #pragma unroll
        for (int o = 4; o <= 16; o <<= 1)
            #pragma unroll
            for (int i = 0; i < 8; i++)
                a[i] += __shfl_xor_sync(FULL, a[i], o);
        if (lane < 4) {
            float* dst = acc + (size_t)lq * 256 + h * 32 + 8 * ch;
            float4 o0; o0.x = a[0]; o0.y = a[1]; o0.z = a[2]; o0.w = a[3];
            float4 o1; o1.x = a[4]; o1.y = a[5]; o1.z = a[6]; o1.w = a[7];
            *reinterpret_cast<float4*>(dst) = o0;
            *reinterpret_cast<float4*>(dst + 4) = o1;
        }
    }
}

// ---------------- fused residual + LayerNorm (warp per row) ----------------
__global__ __launch_bounds__(256)
void ln_kernel(const float* __restrict__ res, const float* __restrict__ y,
               const float* __restrict__ g, const float* __restrict__ b,
               float* __restrict__ out, int M) {
    int warp = (blockIdx.x * blockDim.x + threadIdx.x) >> 5;
    int lane = threadIdx.x & 31;
    if (warp >= M) return;
    const float* r  = res + (size_t)warp * 256;
    const float* yy = y   + (size_t)warp * 256;
    float v[8];
    float s = 0.f;
    #pragma unroll
    for (int i = 0; i < 8; i++) {
        v[i] = r[lane + 32 * i] + yy[lane + 32 * i];
        s += v[i];
    }
    #pragma unroll
    for (int o = 16; o; o >>= 1) s += __shfl_xor_sync(0xffffffffu, s, o);
    float m = s * (1.f / 256.f);
    float vs = 0.f;
    #pragma unroll
    for (int i = 0; i < 8; i++) { float d = v[i] - m; vs += d * d; }
    #pragma unroll
    for (int o = 16; o; o >>= 1) vs += __shfl_xor_sync(0xffffffffu, vs, o);
    float rs = rsqrtf(vs * (1.f / 256.f) + 1e-5f);
    #pragma unroll
    for (int i = 0; i < 8; i++) {
        int c = lane + 32 * i;
        out[(size_t)warp * 256 + c] = (v[i] - m) * rs * g[c] + b[c];
    }
}

// ---------------- host ----------------
extern "C" void kernel_launch(void* const* d_in, const int* in_sizes, int n_in,
                              void* d_out, int out_size) {
    const float* query = (const float*)d_in[0];
    const float* refp  = (const float*)d_in[1];
    const float* pos   = (const float*)d_in[2];
    const int*   shp   = (const int*)d_in[3];
    const int*   sti   = (const int*)d_in[4];
    const float* w_off = (const float*)d_in[5];
    const float* b_off = (const float*)d_in[6];
    const float* w_attn= (const float*)d_in[7];
    const float* b_attn= (const float*)d_in[8];
    const float* w_val = (const float*)d_in[9];
    const float* b_val = (const float*)d_in[10];
    const float* w_out = (const float*)d_in[11];
    const float* b_out = (const float*)d_in[12];
    const float* g1    = (const float*)d_in[13];
    const float* be1   = (const float*)d_in[14];
    const float* w1    = (const float*)d_in[15];
    const float* b1    = (const float*)d_in[16];
    const float* w2    = (const float*)d_in[17];
    const float* b2    = (const float*)d_in[18];
    const float* g2    = (const float*)d_in[19];
    const float* be2   = (const float*)d_in[20];
    float* out = (float*)d_out;

    float *ol, *acc, *x, *h, *f, *wcat, *bcat;
    __nv_bfloat16* valh;
    cudaGetSymbolAddress((void**)&valh, g_valh);
    cudaGetSymbolAddress((void**)&ol,   g_ol);
    cudaGetSymbolAddress((void**)&acc,  g_acc);
    cudaGetSymbolAddress((void**)&x,    g_x);
    cudaGetSymbolAddress((void**)&h,    g_h);
    cudaGetSymbolAddress((void**)&f,    g_f);
    cudaGetSymbolAddress((void**)&wcat, g_wcat);
    cudaGetSymbolAddress((void**)&bcat, g_bcat);

    const int M = LQ;
    dim3 grid_n256(2, (M + 127) / 128);
    dim3 grid_n384(3, (M + 127) / 128);

    cudaStream_t s1;
    cudaStreamCreateWithFlags(&s1, cudaStreamNonBlocking);
    cudaEvent_t e0, e1;
    cudaEventCreateWithFlags(&e0, cudaEventDisableTiming);
    cudaEventCreateWithFlags(&e1, cudaEventDisableTiming);

    cudaEventRecord(e0, 0);
    cudaStreamWaitEvent(s1, e0, 0);
    tgemm<<<grid_n256, 256, 0, s1>>>(query, nullptr, w_val, b_val, valh, M, 256, 2);

    pack_w<<<(256 * 384 + 255) / 256, 256>>>(w_off, b_off, w_attn, b_attn, wcat, bcat);
    tgemm<<<grid_n384, 256>>>(query, pos, wcat, bcat, ol, M, 384, 0);

    cudaEventRecord(e1, s1);
    cudaStreamWaitEvent(0, e1, 0);

    sample_kernel<<<LQ, 256>>>(valh, refp, ol, shp, sti, acc);
    tgemm<<<grid_n256, 256>>>(acc, nullptr, w_out, b_out, f, M, 256, 0);
    {
        int blocks = (M * 32 + 255) / 256;
        ln_kernel<<<blocks, 256>>>(query, f, g1, be1, x, M);
    }
    tgemm<<<grid_n256, 256>>>(x, nullptr, w1, b1, h, M, 256, 1);
    tgemm<<<grid_n256, 256>>>(h, nullptr, w2, b2, f, M, 256, 0);
    {
        int blocks = (M * 32 + 255) / 256;
        ln_kernel<<<blocks, 256>>>(x, f, g2, be2, out, M);
    }
}

// round 9
// speedup vs baseline: 4.3731x; 1.0248x over previous
#include <cuda_runtime.h>
#include <cuda_bf16.h>
#include <cstdint>

#define LQ 43054
#define D  256
#define NH 8
#define NL 4
#define NP 4
#define HD 32

// ---------------- scratch (device globals) ----------------
__device__ __nv_bfloat16 g_valh[LQ * D];
__device__ float g_ol  [LQ * 384];       // [0:256)=offsets, [256:384)=logits
__device__ float g_acc [LQ * D];
__device__ float g_x   [LQ * D];
__device__ float g_h   [LQ * D];
__device__ float g_f   [LQ * D];
__device__ float g_wcat[256 * 384];
__device__ float g_bcat[384];

// ---------------- weight pack: [w_off | w_attn] ----------------
__global__ void pack_w(const float* __restrict__ w_off, const float* __restrict__ b_off,
                       const float* __restrict__ w_attn, const float* __restrict__ b_attn,
                       float* __restrict__ wcat, float* __restrict__ bcat) {
    int i = blockIdx.x * blockDim.x + threadIdx.x;
    if (i >= 256 * 384) return;
    int k = i / 384, n = i % 384;
    wcat[i] = (n < 256) ? w_off[k * 256 + n] : w_attn[k * 128 + (n - 256)];
    if (i < 384) bcat[i] = (i < 256) ? b_off[i] : b_attn[i - 256];
}

// ---------------- bf16 tensor-core GEMM ----------------
// C[M,N] = (A [+ A2])[M,256] @ B[256,N] + bias. BM=128, BN=128, BK=64.
// mode: 0 = fp32 out, 1 = fp32+ReLU, 2 = bf16 out
__global__ __launch_bounds__(256, 2)
void tgemm(const float* __restrict__ A, const float* __restrict__ A2,
           const float* __restrict__ B,
           const float* __restrict__ bias, void* __restrict__ Cv,
           int M, int N, int mode) {
    constexpr int K = 256;
    constexpr int LDA = 72;
    constexpr int LDB = 136;
    __shared__ __align__(16) __nv_bfloat16 As[128 * LDA];
    __shared__ __align__(16) __nv_bfloat16 Bs[64 * LDB];

    int tid = threadIdx.x;
    int lane = tid & 31;
    int wid = tid >> 5;
    int bm = blockIdx.y * 128;
    int bn = blockIdx.x * 128;
    int wm = (wid >> 2) * 64;
    int wn = (wid & 3) * 32;

    float c[4][4][4];
    #pragma unroll
    for (int i = 0; i < 4; i++)
        #pragma unroll
        for (int j = 0; j < 4; j++)
            #pragma unroll
            for (int r = 0; r < 4; r++) c[i][j][r] = 0.f;

    int a_row = lane & 15;
    int a_koff = (lane >> 4) * 8;
    int b_krow = (lane & 7) + ((lane >> 3) & 1) * 8;
    int b_noff = (lane >> 4) * 8;

    for (int k0 = 0; k0 < K; k0 += 64) {
        #pragma unroll
        for (int i = 0; i < 8; i++) {
            int slot = tid + i * 256;
            int row = slot >> 4;
            int k4 = (slot & 15) * 4;
            float4 v = make_float4(0.f, 0.f, 0.f, 0.f);
            if (bm + row < M) {
                v = *reinterpret_cast<const float4*>(A + (size_t)(bm + row) * K + k0 + k4);
                if (A2) {
                    float4 u = *reinterpret_cast<const float4*>(A2 + (size_t)(bm + row) * K + k0 + k4);
                    v.x += u.x; v.y += u.y; v.z += u.z; v.w += u.w;
                }
            }
            __nv_bfloat162 p0 = __floats2bfloat162_rn(v.x, v.y);
            __nv_bfloat162 p1 = __floats2bfloat162_rn(v.z, v.w);
            uint2 st;
            st.x = *reinterpret_cast<uint32_t*>(&p0);
            st.y = *reinterpret_cast<uint32_t*>(&p1);
            *reinterpret_cast<uint2*>(&As[row * LDA + k4]) = st;
        }
        #pragma unroll
        for (int i = 0; i < 8; i++) {
            int slot = tid + i * 256;
            int kk = slot >> 5;
            int n4 = (slot & 31) * 4;
            float4 v = *reinterpret_cast<const float4*>(B + (size_t)(k0 + kk) * N + bn + n4);
            __nv_bfloat162 p0 = __floats2bfloat162_rn(v.x, v.y);
            __nv_bfloat162 p1 = __floats2bfloat162_rn(v.z, v.w);
            uint2 st;
            st.x = *reinterpret_cast<uint32_t*>(&p0);
            st.y = *reinterpret_cast<uint32_t*>(&p1);
            *reinterpret_cast<uint2*>(&Bs[kk * LDB + n4]) = st;
        }
        __syncthreads();

        #pragma unroll
        for (int ks = 0; ks < 4; ks++) {
            int kbase = ks * 16;
            uint32_t af[4][4];
            #pragma unroll
            for (int mf = 0; mf < 4; mf++) {
                const __nv_bfloat16* p = &As[(wm + mf * 16 + a_row) * LDA + kbase + a_koff];
                uint32_t addr = (uint32_t)__cvta_generic_to_shared(p);
                asm volatile("ldmatrix.sync.aligned.m8n8.x4.shared.b16 {%0,%1,%2,%3}, [%4];"
                             : "=r"(af[mf][0]), "=r"(af[mf][1]), "=r"(af[mf][2]), "=r"(af[mf][3])
                             : "r"(addr));
            }
            uint32_t bf[4][2];
            #pragma unroll
            for (int n16 = 0; n16 < 2; n16++) {
                const __nv_bfloat16* p = &Bs[(kbase + b_krow) * LDB + wn + n16 * 16 + b_noff];
                uint32_t addr = (uint32_t)__cvta_generic_to_shared(p);
                asm volatile("ldmatrix.sync.aligned.m8n8.x4.trans.shared.b16 {%0,%1,%2,%3}, [%4];"
                             : "=r"(bf[n16 * 2][0]), "=r"(bf[n16 * 2][1]),
                               "=r"(bf[n16 * 2 + 1][0]), "=r"(bf[n16 * 2 + 1][1])
                             : "r"(addr));
            }
            #pragma unroll
            for (int mf = 0; mf < 4; mf++)
                #pragma unroll
                for (int nf = 0; nf < 4; nf++) {
                    asm volatile(
                        "mma.sync.aligned.m16n8k16.row.col.f32.bf16.bf16.f32 "
                        "{%0,%1,%2,%3}, {%4,%5,%6,%7}, {%8,%9}, {%0,%1,%2,%3};"
                        : "+f"(c[mf][nf][0]), "+f"(c[mf][nf][1]),
                          "+f"(c[mf][nf][2]), "+f"(c[mf][nf][3])
                        : "r"(af[mf][0]), "r"(af[mf][1]), "r"(af[mf][2]), "r"(af[mf][3]),
                          "r"(bf[nf][0]), "r"(bf[nf][1]));
                }
        }
        __syncthreads();
    }

    #pragma unroll
    for (int mf = 0; mf < 4; mf++) {
        int row0 = bm + wm + mf * 16 + (lane >> 2);
        #pragma unroll
        for (int nf = 0; nf < 4; nf++) {
            int col = bn + wn + nf * 8 + (lane & 3) * 2;
            float bx = bias[col], by = bias[col + 1];
            float2 v0, v1;
            v0.x = c[mf][nf][0] + bx; v0.y = c[mf][nf][1] + by;
            v1.x = c[mf][nf][2] + bx; v1.y = c[mf][nf][3] + by;
            if (mode == 1) {
                v0.x = fmaxf(v0.x, 0.f); v0.y = fmaxf(v0.y, 0.f);
                v1.x = fmaxf(v1.x, 0.f); v1.y = fmaxf(v1.y, 0.f);
            }
            if (mode == 2) {
                __nv_bfloat16* C = (__nv_bfloat16*)Cv;
                if (row0 < M)
                    *reinterpret_cast<__nv_bfloat162*>(C + (size_t)row0 * N + col) =
                        __floats2bfloat162_rn(v0.x, v0.y);
                if (row0 + 8 < M)
                    *reinterpret_cast<__nv_bfloat162*>(C + (size_t)(row0 + 8) * N + col) =
                        __floats2bfloat162_rn(v1.x, v1.y);
            } else {
                float* C = (float*)Cv;
                if (row0 < M)
                    *reinterpret_cast<float2*>(C + (size_t)row0 * N + col) = v0;
                if (row0 + 8 < M)
                    *reinterpret_cast<float2*>(C + (size_t)(row0 + 8) * N + col) = v1;
            }
        }
    }
}

// ---------------- deformable sampling ----------
// phase 0: softmax (warp per head); phase 1: per-POINT address math (128 thr);
// phase 2: LDG.128 streaming, pw preloaded to registers.
__global__ __launch_bounds__(256)
void sample_kernel(const __nv_bfloat16* __restrict__ valh,
                   const float* __restrict__ refp,
                   const float* __restrict__ ol,     // (LQ, 384): off | logits
                   const int* __restrict__ shapes,
                   const int* __restrict__ starts,
                   float* __restrict__ acc) {
    __shared__ float aw_s[NH * 16];
    __shared__ __align__(16) int2 pw_s[512];

    int lq = blockIdx.x;
    int tid = threadIdx.x;
    int h = tid >> 5;
    int lane = tid & 31;
    const unsigned FULL = 0xffffffffu;

    // ---- phase 0: softmax per head ----
    {
        const float* lg = ol + (size_t)lq * 384 + 256 + h * 16;
        float myl = (lane < 16) ? lg[lane] : -1e30f;
        float mx = myl;
        #pragma unroll
        for (int o = 8; o; o >>= 1) mx = fmaxf(mx, __shfl_xor_sync(FULL, mx, o));
        float e = (lane < 16) ? __expf(myl - mx) : 0.f;
        float sum = e;
        #pragma unroll
        for (int o = 16; o; o >>= 1) sum += __shfl_xor_sync(FULL, sum, o);
        float inv = 1.f / sum;
        if (lane < 16) aw_s[h * 16 + lane] = e * inv;
    }
    __syncthreads();

    // ---- phase 1: one POINT per thread (tid < 128), emit 4 corners ----
    if (tid < 128) {
        int jh = tid >> 4;          // head
        int p = tid & 15;           // l*4 + pp
        int l = p >> 2;

        int Hl = __ldg(&shapes[l * 2 + 0]);
        int Wl = __ldg(&shapes[l * 2 + 1]);
        int st = __ldg(&starts[l]);
        float fW = (float)Wl, fH = (float)Hl;

        float rx = __ldg(&refp[(size_t)lq * 8 + l * 2 + 0]);
        float ry = __ldg(&refp[(size_t)lq * 8 + l * 2 + 1]);
        float2 oxy = __ldg(reinterpret_cast<const float2*>(ol + (size_t)lq * 384 + jh * 32 + p * 2));

        float x = rx * fW + oxy.x - 0.5f;
        float y = ry * fH + oxy.y - 0.5f;
        float x0f = floorf(x), y0f = floorf(y);
        float fx = x - x0f, fy = y - y0f;
        int x0 = (int)x0f, y0 = (int)y0f;
        float aw = aw_s[jh * 16 + p];

        float wx1 = fx * aw, wx0 = aw - wx1;   // (1-fx)*aw
        float w00 = wx0 * (1.f - fy), w01 = wx1 * (1.f - fy);
        float w10 = wx0 * fy,         w11 = wx1 * fy;

        bool vx0 = (unsigned)x0 < (unsigned)Wl;
        bool vx1 = (unsigned)(x0 + 1) < (unsigned)Wl;
        bool vy0 = (unsigned)y0 < (unsigned)Hl;
        bool vy1 = (unsigned)(y0 + 1) < (unsigned)Hl;
        if (!(vx0 && vy0)) w00 = 0.f;
        if (!(vx1 && vy0)) w01 = 0.f;
        if (!(vx0 && vy1)) w10 = 0.f;
        if (!(vx1 && vy1)) w11 = 0.f;

        int xc0 = min(max(x0, 0), Wl - 1);
        int xc1 = min(max(x0 + 1, 0), Wl - 1);
        int yc0 = min(max(y0, 0), Hl - 1);
        int yc1 = min(max(y0 + 1, 0), Hl - 1);
        int base = st * 512 + jh * 64;          // byte offset base (×2 bytes, ×256 ch)
        int r0 = yc0 * Wl, r1 = yc1 * Wl;

        int4 e0, e1;
        e0.x = base + (r0 + xc0) * 512; e0.y = __float_as_int(w00);
        e0.z = base + (r0 + xc1) * 512; e0.w = __float_as_int(w01);
        e1.x = base + (r1 + xc0) * 512; e1.y = __float_as_int(w10);
        e1.z = base + (r1 + xc1) * 512; e1.w = __float_as_int(w11);
        int4* dst = reinterpret_cast<int4*>(&pw_s[tid * 4]);
        dst[0] = e0;
        dst[1] = e1;
    }
    __syncthreads();

    // ---- phase 2: 8 corners per LDG.128 round ----
    {
        const int2* pw = pw_s + h * 64;
        int cor = lane >> 2;
        int ch = lane & 3;
        const char* vbase = reinterpret_cast<const char*>(valh) + 16 * ch;
        // preload all 8 (addr, weight) pairs
        int2 q[8];
        #pragma unroll
        for (int i = 0; i < 8; i++) q[i] = pw[i * 8 + cor];
        float a[8];
        #pragma unroll
        for (int i = 0; i < 8; i++) a[i] = 0.f;
        #pragma unroll
        for (int i = 0; i < 8; i++) {
            float w = __int_as_float(q[i].y);
            uint4 v = *reinterpret_cast<const uint4*>(vbase + q[i].x);
            float2 f0 = __bfloat1622float2(*reinterpret_cast<__nv_bfloat162*>(&v.x));
            float2 f1 = __bfloat1622float2(*reinterpret_cast<__nv_bfloat162*>(&v.y));
            float2 f2 = __bfloat1622float2(*reinterpret_cast<__nv_bfloat162*>(&v.z));
            float2 f3 = __bfloat1622float2(*reinterpret_cast<__nv_bfloat162*>(&v.w));
            a[0] += w * f0.x; a[1] += w * f0.y;
            a[2] += w * f1.x; a[3] += w * f1.y;
            a[4] += w * f2.x; a[5] += w * f2.y;
            a[6] += w * f3.x; a[7] += w * f3.y;
        }
        #pragma unroll
        for (int o = 4; o <= 16; o <<= 1)
            #pragma unroll
            for (int i = 0; i < 8; i++)
                a[i] += __shfl_xor_sync(FULL, a[i], o);
        if (lane < 4) {
            float* dst = acc + (size_t)lq * 256 + h * 32 + 8 * ch;
            float4 o0; o0.x = a[0]; o0.y = a[1]; o0.z = a[2]; o0.w = a[3];
            float4 o1; o1.x = a[4]; o1.y = a[5]; o1.z = a[6]; o1.w = a[7];
            *reinterpret_cast<float4*>(dst) = o0;
            *reinterpret_cast<float4*>(dst + 4) = o1;
        }
    }
}

// ---------------- fused residual + LayerNorm (warp per row) ----------------
__global__ __launch_bounds__(256)
void ln_kernel(const float* __restrict__ res, const float* __restrict__ y,
               const float* __restrict__ g, const float* __restrict__ b,
               float* __restrict__ out, int M) {
    int warp = (blockIdx.x * blockDim.x + threadIdx.x) >> 5;
    int lane = threadIdx.x & 31;
    if (warp >= M) return;
    const float* r  = res + (size_t)warp * 256;
    const float* yy = y   + (size_t)warp * 256;
    float v[8];
    float s = 0.f;
    #pragma unroll
    for (int i = 0; i < 8; i++) {
        v[i] = __ldg(r + lane + 32 * i) + __ldg(yy + lane + 32 * i);
        s += v[i];
    }
    #pragma unroll
    for (int o = 16; o; o >>= 1) s += __shfl_xor_sync(0xffffffffu, s, o);
    float m = s * (1.f / 256.f);
    float vs = 0.f;
    #pragma unroll
    for (int i = 0; i < 8; i++) { float d = v[i] - m; vs += d * d; }
    #pragma unroll
    for (int o = 16; o; o >>= 1) vs += __shfl_xor_sync(0xffffffffu, vs, o);
    float rs = rsqrtf(vs * (1.f / 256.f) + 1e-5f);
    #pragma unroll
    for (int i = 0; i < 8; i++) {
        int c = lane + 32 * i;
        out[(size_t)warp * 256 + c] = (v[i] - m) * rs * __ldg(g + c) + __ldg(b + c);
    }
}

// ---------------- host ----------------
extern "C" void kernel_launch(void* const* d_in, const int* in_sizes, int n_in,
                              void* d_out, int out_size) {
    const float* query = (const float*)d_in[0];
    const float* refp  = (const float*)d_in[1];
    const float* pos   = (const float*)d_in[2];
    const int*   shp   = (const int*)d_in[3];
    const int*   sti   = (const int*)d_in[4];
    const float* w_off = (const float*)d_in[5];
    const float* b_off = (const float*)d_in[6];
    const float* w_attn= (const float*)d_in[7];
    const float* b_attn= (const float*)d_in[8];
    const float* w_val = (const float*)d_in[9];
    const float* b_val = (const float*)d_in[10];
    const float* w_out = (const float*)d_in[11];
    const float* b_out = (const float*)d_in[12];
    const float* g1    = (const float*)d_in[13];
    const float* be1   = (const float*)d_in[14];
    const float* w1    = (const float*)d_in[15];
    const float* b1    = (const float*)d_in[16];
    const float* w2    = (const float*)d_in[17];
    const float* b2    = (const float*)d_in[18];
    const float* g2    = (const float*)d_in[19];
    const float* be2   = (const float*)d_in[20];
    float* out = (float*)d_out;

    float *ol, *acc, *x, *h, *f, *wcat, *bcat;
    __nv_bfloat16* valh;
    cudaGetSymbolAddress((void**)&valh, g_valh);
    cudaGetSymbolAddress((void**)&ol,   g_ol);
    cudaGetSymbolAddress((void**)&acc,  g_acc);
    cudaGetSymbolAddress((void**)&x,    g_x);
    cudaGetSymbolAddress((void**)&h,    g_h);
    cudaGetSymbolAddress((void**)&f,    g_f);
    cudaGetSymbolAddress((void**)&wcat, g_wcat);
    cudaGetSymbolAddress((void**)&bcat, g_bcat);

    const int M = LQ;
    dim3 grid_n256(2, (M + 127) / 128);
    dim3 grid_n384(3, (M + 127) / 128);

    cudaStream_t s1;
    cudaStreamCreateWithFlags(&s1, cudaStreamNonBlocking);
    cudaEvent_t e0, e1;
    cudaEventCreateWithFlags(&e0, cudaEventDisableTiming);
    cudaEventCreateWithFlags(&e1, cudaEventDisableTiming);

    cudaEventRecord(e0, 0);
    cudaStreamWaitEvent(s1, e0, 0);
    tgemm<<<grid_n256, 256, 0, s1>>>(query, nullptr, w_val, b_val, valh, M, 256, 2);

    pack_w<<<(256 * 384 + 255) / 256, 256>>>(w_off, b_off, w_attn, b_attn, wcat, bcat);
    tgemm<<<grid_n384, 256>>>(query, pos, wcat, bcat, ol, M, 384, 0);

    cudaEventRecord(e1, s1);
    cudaStreamWaitEvent(0, e1, 0);

    sample_kernel<<<LQ, 256>>>(valh, refp, ol, shp, sti, acc);
    tgemm<<<grid_n256, 256>>>(acc, nullptr, w_out, b_out, f, M, 256, 0);
    {
        int blocks = (M * 32 + 255) / 256;
        ln_kernel<<<blocks, 256>>>(query, f, g1, be1, x, M);
    }
    tgemm<<<grid_n256, 256>>>(x, nullptr, w1, b1, h, M, 256, 1);
    tgemm<<<grid_n256, 256>>>(h, nullptr, w2, b2, f, M, 256, 0);
    {
        int blocks = (M * 32 + 255) / 256;
        ln_kernel<<<blocks, 256>>>(x, f, g2, be2, out, M);
    }
}